// round 1
// baseline (speedup 1.0000x reference)
#include <cuda_runtime.h>

#define N_NODES_MAX 100000
#define N_GRAPHS    64

#define CDIV(a, b) (((a) + (b) - 1) / (b))

// ---------------------------------------------------------------------------
// Scratch (static device globals; no allocation allowed)
// ---------------------------------------------------------------------------
__device__ int    g_deg[N_NODES_MAX];
__device__ float  g_dinv[N_NODES_MAX];
__device__ float4 g_hs1[N_NODES_MAX * 4];   // dinv-scaled layer1 features [N,16]
__device__ float4 g_accA[N_NODES_MAX * 4];  // layer1 aggregation accumulator
__device__ float4 g_hs2[N_NODES_MAX * 8];   // dinv-scaled layer2 features [N,32]
__device__ float4 g_accB[N_NODES_MAX * 8];  // layer2 aggregation accumulator
__device__ float  g_pool[N_GRAPHS * 32];
__device__ float  g_cnt[N_GRAPHS];

// ---------------------------------------------------------------------------
// Vector atomic add (sm_90+): one red.v4 instead of 4 scalar atomics
// ---------------------------------------------------------------------------
__device__ __forceinline__ void red_add_v4(float4* p, float4 v) {
    asm volatile("red.global.add.v4.f32 [%0], {%1, %2, %3, %4};"
                 :: "l"(p), "f"(v.x), "f"(v.y), "f"(v.z), "f"(v.w)
                 : "memory");
}

// ---------------------------------------------------------------------------
// 0) init: deg = 1 (self loop), pool/cnt = 0
// ---------------------------------------------------------------------------
__global__ void k_init(int n) {
    int i = blockIdx.x * blockDim.x + threadIdx.x;
    if (i < n)              g_deg[i] = 1;
    if (i < N_GRAPHS * 32)  g_pool[i] = 0.0f;
    if (i < N_GRAPHS)       g_cnt[i] = 0.0f;
}

// 1) degree count over dst
__global__ void k_deg(const int* __restrict__ dst, int E) {
    int e = blockIdx.x * blockDim.x + threadIdx.x;
    if (e < E) atomicAdd(&g_deg[dst[e]], 1);
}

// 2) dinv = rsqrt(deg)
__global__ void k_dinv(int n) {
    int i = blockIdx.x * blockDim.x + threadIdx.x;
    if (i < n) g_dinv[i] = rsqrtf((float)g_deg[i]);
}

// ---------------------------------------------------------------------------
// 3) GEMM1: hs1 = dinv * (x @ W1)  [N,128]x[128,16]; accA initialized = hs1
//    Block: 128 threads, 64 rows/block, 2 rows per thread, 4 cols (1 float4).
// ---------------------------------------------------------------------------
__global__ __launch_bounds__(128) void k_gemm1(const float* __restrict__ x,
                                               const float* __restrict__ W1,
                                               int n) {
    __shared__ float4 xs[64 * 33];  // 64 rows, stride 33 f4 (pad -> conflict free)
    __shared__ float4 Ws[512];      // W1: 128x16 floats

    int tid  = threadIdx.x;
    int base = blockIdx.x * 64;

    const float4* W4 = (const float4*)W1;
    #pragma unroll
    for (int i = tid; i < 512; i += 128) Ws[i] = W4[i];

    const float4* x4 = (const float4*)x;
    for (int i = tid; i < 64 * 32; i += 128) {
        int r = i >> 5, c = i & 31;
        float4 v = make_float4(0.f, 0.f, 0.f, 0.f);
        if (base + r < n) v = x4[(size_t)(base + r) * 32 + c];
        xs[r * 33 + c] = v;
    }
    __syncthreads();

    int jg = tid & 3;        // which float4 of 16 outputs
    int rg = tid >> 2;       // 0..31; handles rows rg and rg+32

    float4 a0 = make_float4(0.f, 0.f, 0.f, 0.f);
    float4 a1 = a0;

    #pragma unroll 8
    for (int c4 = 0; c4 < 32; c4++) {
        float4 xv0 = xs[rg * 33 + c4];
        float4 xv1 = xs[(rg + 32) * 33 + c4];
        float e0[4] = {xv0.x, xv0.y, xv0.z, xv0.w};
        float e1[4] = {xv1.x, xv1.y, xv1.z, xv1.w};
        #pragma unroll
        for (int k = 0; k < 4; k++) {
            float4 w = Ws[(c4 * 4 + k) * 4 + jg];
            a0.x = fmaf(e0[k], w.x, a0.x); a0.y = fmaf(e0[k], w.y, a0.y);
            a0.z = fmaf(e0[k], w.z, a0.z); a0.w = fmaf(e0[k], w.w, a0.w);
            a1.x = fmaf(e1[k], w.x, a1.x); a1.y = fmaf(e1[k], w.y, a1.y);
            a1.z = fmaf(e1[k], w.z, a1.z); a1.w = fmaf(e1[k], w.w, a1.w);
        }
    }

    int r0 = base + rg, r1 = base + rg + 32;
    if (r0 < n) {
        float di = g_dinv[r0];
        float4 v = make_float4(a0.x * di, a0.y * di, a0.z * di, a0.w * di);
        g_hs1[r0 * 4 + jg] = v;
        g_accA[r0 * 4 + jg] = v;   // self-loop term
    }
    if (r1 < n) {
        float di = g_dinv[r1];
        float4 v = make_float4(a1.x * di, a1.y * di, a1.z * di, a1.w * di);
        g_hs1[r1 * 4 + jg] = v;
        g_accA[r1 * 4 + jg] = v;
    }
}

// ---------------------------------------------------------------------------
// 4) Scatter layer 1: accA[dst] += hs1[src]   (4 threads/edge, v4 atomics)
// ---------------------------------------------------------------------------
__global__ void k_scatter1(const int* __restrict__ src,
                           const int* __restrict__ dst, int E) {
    int idx = blockIdx.x * blockDim.x + threadIdx.x;
    int e = idx >> 2;
    if (e >= E) return;
    int c = idx & 3;
    int s = src[e], d = dst[e];
    float4 v = __ldg(&g_hs1[s * 4 + c]);
    red_add_v4(&g_accA[d * 4 + c], v);
}

// ---------------------------------------------------------------------------
// 5) GEMM2: h1 = relu(dinv*accA + b1) fused into tile load;
//    hs2 = dinv * (h1 @ W2)  [N,16]x[16,32]; accB = hs2.
//    Block: 256 threads, 32 rows/block, 1 row x 4 cols per thread.
// ---------------------------------------------------------------------------
__global__ __launch_bounds__(256) void k_gemm2(const float* __restrict__ b1,
                                               const float* __restrict__ W2,
                                               int n) {
    __shared__ float4 xs[32 * 5];  // 32 rows x (4 data + 1 pad) f4
    __shared__ float4 Ws[128];     // W2: 16x32 floats

    int tid  = threadIdx.x;
    int base = blockIdx.x * 32;

    const float4* W4 = (const float4*)W2;
    if (tid < 128) Ws[tid] = W4[tid];

    const float4* b1_4 = (const float4*)b1;
    if (tid < 128) {  // 32 rows * 4 f4
        int r = tid >> 2, c4 = tid & 3;
        float4 v = make_float4(0.f, 0.f, 0.f, 0.f);
        if (base + r < n) {
            float4 a  = g_accA[(base + r) * 4 + c4];
            float  di = g_dinv[base + r];
            float4 bb = __ldg(&b1_4[c4]);
            v.x = fmaxf(fmaf(di, a.x, bb.x), 0.f);
            v.y = fmaxf(fmaf(di, a.y, bb.y), 0.f);
            v.z = fmaxf(fmaf(di, a.z, bb.z), 0.f);
            v.w = fmaxf(fmaf(di, a.w, bb.w), 0.f);
        }
        xs[r * 5 + c4] = v;
    }
    __syncthreads();

    int jg = tid & 7;    // which float4 of 32 outputs
    int rg = tid >> 3;   // 0..31

    float4 acc = make_float4(0.f, 0.f, 0.f, 0.f);
    #pragma unroll
    for (int c4 = 0; c4 < 4; c4++) {
        float4 xv = xs[rg * 5 + c4];
        float e[4] = {xv.x, xv.y, xv.z, xv.w};
        #pragma unroll
        for (int k = 0; k < 4; k++) {
            float4 w = Ws[(c4 * 4 + k) * 8 + jg];
            acc.x = fmaf(e[k], w.x, acc.x); acc.y = fmaf(e[k], w.y, acc.y);
            acc.z = fmaf(e[k], w.z, acc.z); acc.w = fmaf(e[k], w.w, acc.w);
        }
    }

    int row = base + rg;
    if (row < n) {
        float di = g_dinv[row];
        float4 v = make_float4(acc.x * di, acc.y * di, acc.z * di, acc.w * di);
        g_hs2[row * 8 + jg] = v;
        g_accB[row * 8 + jg] = v;   // self-loop term
    }
}

// ---------------------------------------------------------------------------
// 6) Scatter layer 2: accB[dst] += hs2[src]   (8 threads/edge, v4 atomics)
// ---------------------------------------------------------------------------
__global__ void k_scatter2(const int* __restrict__ src,
                           const int* __restrict__ dst, int E) {
    int idx = blockIdx.x * blockDim.x + threadIdx.x;
    int e = idx >> 3;
    if (e >= E) return;
    int c = idx & 7;
    int s = src[e], d = dst[e];
    float4 v = __ldg(&g_hs2[s * 8 + c]);
    red_add_v4(&g_accB[d * 8 + c], v);
}

// ---------------------------------------------------------------------------
// 7) Fused layer-2 epilogue + global mean pool (sums & counts).
//    Warp = one node's 32 features. batch is sorted -> register-accumulate
//    per graph, flush on change (few global atomics).
// ---------------------------------------------------------------------------
__global__ __launch_bounds__(256) void k_pool(const int* __restrict__ batch,
                                              const float* __restrict__ b2,
                                              int n) {
    int f    = threadIdx.x & 31;
    int sub  = threadIdx.x >> 5;         // warp id within block (0..7)
    int base = blockIdx.x * 256;
    float bb = __ldg(&b2[f]);
    const float* accB = (const float*)g_accB;

    int cur = -1;
    float rsum = 0.f, rcnt = 0.f;

    for (int it = 0; it < 32; it++) {
        int i = base + it * 8 + sub;
        if (i < n) {
            int g = batch[i];
            if (g != cur) {
                if (cur >= 0) {
                    atomicAdd(&g_pool[cur * 32 + f], rsum);
                    if (f == 0) atomicAdd(&g_cnt[cur], rcnt);
                }
                cur = g; rsum = 0.f; rcnt = 0.f;
            }
            float v = fmaxf(fmaf(g_dinv[i], accB[(size_t)i * 32 + f], bb), 0.f);
            rsum += v;
            rcnt += 1.f;
        }
    }
    if (cur >= 0) {
        atomicAdd(&g_pool[cur * 32 + f], rsum);
        if (f == 0) atomicAdd(&g_cnt[cur], rcnt);
    }
}

// ---------------------------------------------------------------------------
// 8) MLP head: g=[64,32] mean -> relu(g@Wf1+bf1) -> @Wf2+bf2 -> out [64,8]
//    One block, one thread per graph.
// ---------------------------------------------------------------------------
__global__ __launch_bounds__(64) void k_mlp(const float* __restrict__ Wf1,
                                            const float* __restrict__ bf1,
                                            const float* __restrict__ Wf2,
                                            const float* __restrict__ bf2,
                                            float* __restrict__ out) {
    int g = threadIdx.x;
    if (g >= N_GRAPHS) return;

    float inv = 1.0f / fmaxf(g_cnt[g], 1.0f);
    float gv[32];
    #pragma unroll
    for (int c = 0; c < 32; c++) gv[c] = g_pool[g * 32 + c] * inv;

    float h[64];
    #pragma unroll 8
    for (int j = 0; j < 64; j++) {
        float s = __ldg(&bf1[j]);
        #pragma unroll
        for (int c = 0; c < 32; c++) s = fmaf(gv[c], __ldg(&Wf1[c * 64 + j]), s);
        h[j] = fmaxf(s, 0.f);
    }

    #pragma unroll
    for (int o = 0; o < 8; o++) {
        float s = __ldg(&bf2[o]);
        #pragma unroll 16
        for (int j = 0; j < 64; j++) s = fmaf(h[j], __ldg(&Wf2[j * 8 + o]), s);
        out[g * 8 + o] = s;
    }
}

// ---------------------------------------------------------------------------
// Launch
// ---------------------------------------------------------------------------
extern "C" void kernel_launch(void* const* d_in, const int* in_sizes, int n_in,
                              void* d_out, int out_size) {
    const float* x     = (const float*)d_in[0];
    const int*   ei    = (const int*)  d_in[1];
    const int*   batch = (const int*)  d_in[2];
    const float* W1    = (const float*)d_in[3];
    const float* b1    = (const float*)d_in[4];
    const float* W2    = (const float*)d_in[5];
    const float* b2    = (const float*)d_in[6];
    const float* Wf1   = (const float*)d_in[7];
    const float* bf1   = (const float*)d_in[8];
    const float* Wf2   = (const float*)d_in[9];
    const float* bf2   = (const float*)d_in[10];
    float* out = (float*)d_out;

    int N = in_sizes[0] / 128;
    int E = in_sizes[1] / 2;
    const int* src = ei;
    const int* dst = ei + E;

    k_init<<<CDIV(N, 256), 256>>>(N);
    k_deg<<<CDIV(E, 256), 256>>>(dst, E);
    k_dinv<<<CDIV(N, 256), 256>>>(N);

    k_gemm1<<<CDIV(N, 64), 128>>>(x, W1, N);
    k_scatter1<<<CDIV(E * 4, 256), 256>>>(src, dst, E);

    k_gemm2<<<CDIV(N, 32), 256>>>(b1, W2, N);
    k_scatter2<<<CDIV(E * 8, 256), 256>>>(src, dst, E);

    k_pool<<<CDIV(N, 256), 256>>>(batch, b2, N);
    k_mlp<<<1, 64>>>(Wf1, bf1, Wf2, bf2, out);
}

// round 3
// speedup vs baseline: 1.2071x; 1.2071x over previous
#include <cuda_runtime.h>

#define N_NODES_MAX 100000
#define N_GRAPHS    64

#define CDIV(a, b) (((a) + (b) - 1) / (b))

// ---------------------------------------------------------------------------
// Scratch (static device globals; no allocation allowed)
// ---------------------------------------------------------------------------
__device__ int    g_deg[N_NODES_MAX];
__device__ float  g_dinv[N_NODES_MAX];
__device__ float4 g_hs1[N_NODES_MAX * 4];   // dinv-scaled layer1 features [N,16]
__device__ float4 g_accA[N_NODES_MAX * 4];  // layer1 aggregation accumulator
__device__ float4 g_p2[N_NODES_MAX * 4];    // dinv-scaled layer2 INPUT [N,16]
__device__ float4 g_accB[N_NODES_MAX * 4];  // layer2 aggregation accumulator (16 feats)
__device__ float  g_pool[N_GRAPHS * 32];
__device__ float  g_cnt[N_GRAPHS];

// ---------------------------------------------------------------------------
// Vector atomic add (sm_90+): one red.v4 instead of 4 scalar atomics
// ---------------------------------------------------------------------------
__device__ __forceinline__ void red_add_v4(float4* p, float4 v) {
    asm volatile("red.global.add.v4.f32 [%0], {%1, %2, %3, %4};"
                 :: "l"(p), "f"(v.x), "f"(v.y), "f"(v.z), "f"(v.w)
                 : "memory");
}

// ---------------------------------------------------------------------------
// 0) init: deg = 1 (self loop), pool/cnt = 0
// ---------------------------------------------------------------------------
__global__ void k_init(int n) {
    int i = blockIdx.x * blockDim.x + threadIdx.x;
    if (i < n)              g_deg[i] = 1;
    if (i < N_GRAPHS * 32)  g_pool[i] = 0.0f;
    if (i < N_GRAPHS)       g_cnt[i] = 0.0f;
}

// 1) degree count over dst
__global__ void k_deg(const int* __restrict__ dst, int E) {
    int e = blockIdx.x * blockDim.x + threadIdx.x;
    if (e < E) atomicAdd(&g_deg[dst[e]], 1);
}

// 2) dinv = rsqrt(deg)
__global__ void k_dinv(int n) {
    int i = blockIdx.x * blockDim.x + threadIdx.x;
    if (i < n) g_dinv[i] = rsqrtf((float)g_deg[i]);
}

// ---------------------------------------------------------------------------
// 3) GEMM1: hs1 = dinv * (x @ W1)  [N,128]x[128,16]; accA initialized = hs1
//    256 threads, 64 rows/block, K chunked in 2 halves -> 25.6KB smem,
//    8 blocks/SM (full occupancy). Thread = (row rg, output-f4 jg).
// ---------------------------------------------------------------------------
__global__ __launch_bounds__(256) void k_gemm1(const float* __restrict__ x,
                                               const float* __restrict__ W1,
                                               int n) {
    __shared__ float4 xs[64 * 17];  // 64 rows x 16 f4 (+1 pad) = 17.4KB
    __shared__ float4 Ws[512];      // full W1: 128x16 floats = 8KB

    int tid  = threadIdx.x;
    int base = blockIdx.x * 64;

    const float4* W4 = (const float4*)W1;
    #pragma unroll
    for (int i = tid; i < 512; i += 256) Ws[i] = W4[i];

    int rg = tid >> 2;   // row 0..63
    int jg = tid & 3;    // output f4 0..3

    const float4* x4 = (const float4*)x;
    float4 acc = make_float4(0.f, 0.f, 0.f, 0.f);

    #pragma unroll
    for (int chunk = 0; chunk < 2; chunk++) {
        __syncthreads();  // Ws ready (chunk0) / xs consumed (chunk1)
        #pragma unroll
        for (int i = tid; i < 64 * 16; i += 256) {
            int r = i >> 4, c = i & 15;
            float4 v = make_float4(0.f, 0.f, 0.f, 0.f);
            if (base + r < n) v = x4[(size_t)(base + r) * 32 + chunk * 16 + c];
            xs[r * 17 + c] = v;
        }
        __syncthreads();

        #pragma unroll 4
        for (int c4 = 0; c4 < 16; c4++) {
            float4 xv = xs[rg * 17 + c4];
            float e[4] = {xv.x, xv.y, xv.z, xv.w};
            #pragma unroll
            for (int k = 0; k < 4; k++) {
                float4 w = Ws[(chunk * 64 + c4 * 4 + k) * 4 + jg];
                acc.x = fmaf(e[k], w.x, acc.x); acc.y = fmaf(e[k], w.y, acc.y);
                acc.z = fmaf(e[k], w.z, acc.z); acc.w = fmaf(e[k], w.w, acc.w);
            }
        }
    }

    int r0 = base + rg;
    if (r0 < n) {
        float di = g_dinv[r0];
        float4 v = make_float4(acc.x * di, acc.y * di, acc.z * di, acc.w * di);
        g_hs1[r0 * 4 + jg] = v;
        g_accA[r0 * 4 + jg] = v;   // self-loop term
    }
}

// ---------------------------------------------------------------------------
// 4) Scatter layer 1: accA[dst] += hs1[src]  (4 threads/edge, v4 atomics)
//    NOTE: device globals referenced INSIDE device code — never passed as
//    kernel args from host (host-side symbol address is the host shadow).
// ---------------------------------------------------------------------------
__global__ void k_scatter1(const int* __restrict__ src,
                           const int* __restrict__ dst, int E) {
    int idx = blockIdx.x * blockDim.x + threadIdx.x;
    int e = idx >> 2;
    if (e >= E) return;
    int c = idx & 3;
    int s = src[e], d = dst[e];
    float4 v = __ldg(&g_hs1[s * 4 + c]);
    red_add_v4(&g_accA[d * 4 + c], v);
}

// ---------------------------------------------------------------------------
// 5) Layer-1 epilogue -> layer-2 pre-scale (elementwise):
//    h1 = relu(dinv*accA + b1);  p2 = dinv * h1;  accB = p2 (self loop)
// ---------------------------------------------------------------------------
__global__ void k_post1(const float* __restrict__ b1, int n) {
    int i = blockIdx.x * blockDim.x + threadIdx.x;
    if (i >= n * 4) return;
    int r = i >> 2, c4 = i & 3;
    float di = g_dinv[r];
    float4 a = g_accA[i];
    float4 bb = __ldg(&((const float4*)b1)[c4]);
    float4 v;
    v.x = di * fmaxf(fmaf(di, a.x, bb.x), 0.f);
    v.y = di * fmaxf(fmaf(di, a.y, bb.y), 0.f);
    v.z = di * fmaxf(fmaf(di, a.z, bb.z), 0.f);
    v.w = di * fmaxf(fmaf(di, a.w, bb.w), 0.f);
    g_p2[i] = v;
    g_accB[i] = v;
}

// ---------------------------------------------------------------------------
// 6) Scatter layer 2: accB[dst] += p2[src]  (16 features only — aggregation
//    moved BEFORE the W2 multiply; halves traffic vs 32-feat scatter)
// ---------------------------------------------------------------------------
__global__ void k_scatter2(const int* __restrict__ src,
                           const int* __restrict__ dst, int E) {
    int idx = blockIdx.x * blockDim.x + threadIdx.x;
    int e = idx >> 2;
    if (e >= E) return;
    int c = idx & 3;
    int s = src[e], d = dst[e];
    float4 v = __ldg(&g_p2[s * 4 + c]);
    red_add_v4(&g_accB[d * 4 + c], v);
}

// ---------------------------------------------------------------------------
// 7) Fused layer-2 GEMM (@W2 + b2 + relu) + global mean pool.
//    Warp = one node per iteration; lane = output feature (32).
//    Row of dinv*accB held in lanes 0-15, shfl-broadcast into FMA loop.
//    batch sorted -> register accumulation per graph, flush on change.
// ---------------------------------------------------------------------------
__global__ __launch_bounds__(256) void k_pool(const int* __restrict__ batch,
                                              const float* __restrict__ W2,
                                              const float* __restrict__ b2,
                                              int n) {
    __shared__ float W2s[512];  // 16x32
    int tid = threadIdx.x;
    #pragma unroll
    for (int i = tid; i < 512; i += 256) W2s[i] = W2[i];
    __syncthreads();

    int lane = tid & 31;
    int sub  = tid >> 5;         // warp id in block (0..7)
    int base = blockIdx.x * 256;
    float bb = __ldg(&b2[lane]);
    const float* accB = (const float*)g_accB;

    int cur = -1;
    float rsum = 0.f, rcnt = 0.f;

    for (int it = 0; it < 32; it++) {
        int i = base + it * 8 + sub;
        if (i < n) {
            int g = batch[i];
            if (g != cur) {
                if (cur >= 0) {
                    atomicAdd(&g_pool[cur * 32 + lane], rsum);
                    if (lane == 0) atomicAdd(&g_cnt[cur], rcnt);
                }
                cur = g; rsum = 0.f; rcnt = 0.f;
            }
            float di  = g_dinv[i];
            float myv = 0.f;
            if (lane < 16) myv = accB[(size_t)i * 16 + lane] * di;
            float acc = bb;
            #pragma unroll
            for (int k = 0; k < 16; k++) {
                float vk = __shfl_sync(0xffffffffu, myv, k);
                acc = fmaf(vk, W2s[k * 32 + lane], acc);
            }
            rsum += fmaxf(acc, 0.f);
            rcnt += 1.f;
        }
    }
    if (cur >= 0) {
        atomicAdd(&g_pool[cur * 32 + lane], rsum);
        if (lane == 0) atomicAdd(&g_cnt[cur], rcnt);
    }
}

// ---------------------------------------------------------------------------
// 8) MLP head: g=[64,32] mean -> relu(g@Wf1+bf1) -> @Wf2+bf2 -> out [64,8]
// ---------------------------------------------------------------------------
__global__ __launch_bounds__(64) void k_mlp(const float* __restrict__ Wf1,
                                            const float* __restrict__ bf1,
                                            const float* __restrict__ Wf2,
                                            const float* __restrict__ bf2,
                                            float* __restrict__ out) {
    int g = threadIdx.x;
    if (g >= N_GRAPHS) return;

    float inv = 1.0f / fmaxf(g_cnt[g], 1.0f);
    float gv[32];
    #pragma unroll
    for (int c = 0; c < 32; c++) gv[c] = g_pool[g * 32 + c] * inv;

    float h[64];
    #pragma unroll 8
    for (int j = 0; j < 64; j++) {
        float s = __ldg(&bf1[j]);
        #pragma unroll
        for (int c = 0; c < 32; c++) s = fmaf(gv[c], __ldg(&Wf1[c * 64 + j]), s);
        h[j] = fmaxf(s, 0.f);
    }

    #pragma unroll
    for (int o = 0; o < 8; o++) {
        float s = __ldg(&bf2[o]);
        #pragma unroll 16
        for (int j = 0; j < 64; j++) s = fmaf(h[j], __ldg(&Wf2[j * 8 + o]), s);
        out[g * 8 + o] = s;
    }
}

// ---------------------------------------------------------------------------
// Launch
// ---------------------------------------------------------------------------
extern "C" void kernel_launch(void* const* d_in, const int* in_sizes, int n_in,
                              void* d_out, int out_size) {
    const float* x     = (const float*)d_in[0];
    const int*   ei    = (const int*)  d_in[1];
    const int*   batch = (const int*)  d_in[2];
    const float* W1    = (const float*)d_in[3];
    const float* b1    = (const float*)d_in[4];
    const float* W2    = (const float*)d_in[5];
    const float* b2    = (const float*)d_in[6];
    const float* Wf1   = (const float*)d_in[7];
    const float* bf1   = (const float*)d_in[8];
    const float* Wf2   = (const float*)d_in[9];
    const float* bf2   = (const float*)d_in[10];
    float* out = (float*)d_out;

    int N = in_sizes[0] / 128;
    int E = in_sizes[1] / 2;
    const int* src = ei;
    const int* dst = ei + E;

    k_init<<<CDIV(N, 256), 256>>>(N);
    k_deg<<<CDIV(E, 256), 256>>>(dst, E);
    k_dinv<<<CDIV(N, 256), 256>>>(N);

    k_gemm1<<<CDIV(N, 64), 256>>>(x, W1, N);
    k_scatter1<<<CDIV(E * 4, 256), 256>>>(src, dst, E);

    k_post1<<<CDIV(N * 4, 256), 256>>>(b1, N);
    k_scatter2<<<CDIV(E * 4, 256), 256>>>(src, dst, E);

    k_pool<<<CDIV(N, 256), 256>>>(batch, W2, b2, N);
    k_mlp<<<1, 64>>>(Wf1, bf1, Wf2, bf2, out);
}

// round 4
// speedup vs baseline: 1.2111x; 1.0033x over previous
#include <cuda_runtime.h>

#define N_NODES_MAX 100000
#define N_EDGES_MAX 3200000
#define N_GRAPHS    64

#define CDIV(a, b) (((a) + (b) - 1) / (b))

// ---------------------------------------------------------------------------
// Scratch (static device globals; no allocation allowed)
// ---------------------------------------------------------------------------
__device__ int    g_deg[N_NODES_MAX];       // indegree + 1 (self loop)
__device__ float  g_dinv[N_NODES_MAX];
__device__ int    g_start[N_NODES_MAX];     // CSR segment start
__device__ int    g_cur[N_NODES_MAX];       // CSR fill cursor
__device__ int    g_csr[N_EDGES_MAX];       // src indices grouped by dst
__device__ int    g_cursor;                 // global CSR allocator
__device__ float4 g_hs1[N_NODES_MAX * 4];   // dinv-scaled layer1 features [N,16]
__device__ float4 g_p2[N_NODES_MAX * 4];    // dinv-scaled layer2 input [N,16]
__device__ float4 g_accB[N_NODES_MAX * 4];  // layer2 aggregate (16 feats)
__device__ float  g_pool[N_GRAPHS * 32];
__device__ float  g_cnt[N_GRAPHS];

// ---------------------------------------------------------------------------
// 0) init
// ---------------------------------------------------------------------------
__global__ void k_init(int n) {
    int i = blockIdx.x * blockDim.x + threadIdx.x;
    if (i < n)              g_deg[i] = 1;
    if (i < N_GRAPHS * 32)  g_pool[i] = 0.0f;
    if (i < N_GRAPHS)       g_cnt[i] = 0.0f;
    if (i == 0)             g_cursor = 0;
}

// 1) degree count over dst
__global__ void k_deg(const int* __restrict__ dst, int E) {
    int e = blockIdx.x * blockDim.x + threadIdx.x;
    if (e < E) atomicAdd(&g_deg[dst[e]], 1);
}

// 2) dinv = rsqrt(deg)
__global__ void k_dinv(int n) {
    int i = blockIdx.x * blockDim.x + threadIdx.x;
    if (i < n) g_dinv[i] = rsqrtf((float)g_deg[i]);
}

// ---------------------------------------------------------------------------
// 3) CSR slot allocation: warp-aggregated prefix over (deg-1).
//    Segment order is arbitrary (valid CSR: each node gets a contiguous run).
// ---------------------------------------------------------------------------
__global__ void k_alloc(int n) {
    int i    = blockIdx.x * blockDim.x + threadIdx.x;
    int lane = threadIdx.x & 31;
    int cnt  = (i < n) ? (g_deg[i] - 1) : 0;
    int v = cnt;  // inclusive scan within warp
    #pragma unroll
    for (int o = 1; o < 32; o <<= 1) {
        int t = __shfl_up_sync(0xffffffffu, v, o);
        if (lane >= o) v += t;
    }
    int total = __shfl_sync(0xffffffffu, v, 31);
    int base = 0;
    if (lane == 0) base = atomicAdd(&g_cursor, total);
    base = __shfl_sync(0xffffffffu, base, 0);
    if (i < n) {
        int st = base + v - cnt;   // exclusive
        g_start[i] = st;
        g_cur[i]   = st;
    }
}

// 4) CSR placement: csr[cursor(dst)++] = src
__global__ void k_place(const int* __restrict__ src,
                        const int* __restrict__ dst, int E) {
    int e = blockIdx.x * blockDim.x + threadIdx.x;
    if (e >= E) return;
    int d = dst[e];
    int pos = atomicAdd(&g_cur[d], 1);
    g_csr[pos] = src[e];
}

// ---------------------------------------------------------------------------
// 5) GEMM1: hs1 = dinv * (x @ W1)  [N,128]x[128,16]
//    256 threads, 256 rows/block. Thread = (rg = tid>>2, jg = tid&3),
//    handles rows {rg, rg+64, rg+128, rg+192}. K chunked by 32.
//    Balanced pipes: per c4, 8 LDS.128 (4 xs + 4 Ws) for 64 FFMA.
//    xs transposed + XOR swizzle: conflict-free loads, 4-phase stores.
// ---------------------------------------------------------------------------
__global__ __launch_bounds__(256, 4) void k_gemm1(const float* __restrict__ x,
                                                  const float* __restrict__ W1,
                                                  int n) {
    __shared__ float4 xs[8 * 256];  // [c (0..7)][row (0..255)] swizzled, 32KB
    __shared__ float4 Ws[512];      // full W1: 128x16 floats = 8KB

    int tid  = threadIdx.x;
    int base = blockIdx.x * 256;
    int rg = tid >> 2;   // 0..63
    int jg = tid & 3;    // output f4 0..3

    const float4* W4 = (const float4*)W1;
    Ws[tid]       = W4[tid];
    Ws[tid + 256] = W4[tid + 256];

    const float4* x4 = (const float4*)x;
    float4 acc[4];
    #pragma unroll
    for (int rr = 0; rr < 4; rr++) acc[rr] = make_float4(0.f, 0.f, 0.f, 0.f);

    #pragma unroll
    for (int chunk = 0; chunk < 4; chunk++) {
        __syncthreads();  // Ws ready / xs consumed
        #pragma unroll
        for (int m = 0; m < 8; m++) {
            int i   = m * 256 + tid;
            int row = i >> 3, c = i & 7;
            float4 v = make_float4(0.f, 0.f, 0.f, 0.f);
            if (base + row < n) v = x4[(size_t)(base + row) * 32 + chunk * 8 + c];
            xs[c * 256 + (row ^ c)] = v;
        }
        __syncthreads();

        #pragma unroll
        for (int c4 = 0; c4 < 8; c4++) {
            float4 xv[4];
            #pragma unroll
            for (int rr = 0; rr < 4; rr++)
                xv[rr] = xs[c4 * 256 + ((rr * 64 + rg) ^ c4)];
            #pragma unroll
            for (int kk = 0; kk < 4; kk++) {
                float4 w = Ws[(chunk * 32 + c4 * 4 + kk) * 4 + jg];
                #pragma unroll
                for (int rr = 0; rr < 4; rr++) {
                    float e = (kk == 0) ? xv[rr].x : (kk == 1) ? xv[rr].y
                            : (kk == 2) ? xv[rr].z : xv[rr].w;
                    acc[rr].x = fmaf(e, w.x, acc[rr].x);
                    acc[rr].y = fmaf(e, w.y, acc[rr].y);
                    acc[rr].z = fmaf(e, w.z, acc[rr].z);
                    acc[rr].w = fmaf(e, w.w, acc[rr].w);
                }
            }
        }
    }

    #pragma unroll
    for (int rr = 0; rr < 4; rr++) {
        int r = base + rr * 64 + rg;
        if (r < n) {
            float di = g_dinv[r];
            g_hs1[r * 4 + jg] = make_float4(acc[rr].x * di, acc[rr].y * di,
                                            acc[rr].z * di, acc[rr].w * di);
        }
    }
}

// ---------------------------------------------------------------------------
// 6) Layer-1 aggregation (gather, NO atomics) + fused epilogue.
//    4 threads per node (c = lane&3); acc = self + sum over CSR neighbors.
//    Epilogue: p2 = dinv * relu(dinv*acc + b1).
// ---------------------------------------------------------------------------
__global__ __launch_bounds__(256) void k_agg1(const float* __restrict__ b1, int n) {
    int t = blockIdx.x * blockDim.x + threadIdx.x;
    int node = t >> 2;
    if (node >= n) return;
    int c = t & 3;

    int st  = g_start[node];
    int cnt = g_deg[node] - 1;
    float4 a = g_hs1[node * 4 + c];   // self-loop term

    int j = 0;
    for (; j + 4 <= cnt; j += 4) {
        int s0 = __ldg(&g_csr[st + j]);
        int s1 = __ldg(&g_csr[st + j + 1]);
        int s2 = __ldg(&g_csr[st + j + 2]);
        int s3 = __ldg(&g_csr[st + j + 3]);
        float4 v0 = __ldg(&g_hs1[s0 * 4 + c]);
        float4 v1 = __ldg(&g_hs1[s1 * 4 + c]);
        float4 v2 = __ldg(&g_hs1[s2 * 4 + c]);
        float4 v3 = __ldg(&g_hs1[s3 * 4 + c]);
        a.x += v0.x + v1.x + v2.x + v3.x;
        a.y += v0.y + v1.y + v2.y + v3.y;
        a.z += v0.z + v1.z + v2.z + v3.z;
        a.w += v0.w + v1.w + v2.w + v3.w;
    }
    for (; j < cnt; j++) {
        int s = __ldg(&g_csr[st + j]);
        float4 v = __ldg(&g_hs1[s * 4 + c]);
        a.x += v.x; a.y += v.y; a.z += v.z; a.w += v.w;
    }

    float di = g_dinv[node];
    float4 bb = __ldg(&((const float4*)b1)[c]);
    float4 o;
    o.x = di * fmaxf(fmaf(di, a.x, bb.x), 0.f);
    o.y = di * fmaxf(fmaf(di, a.y, bb.y), 0.f);
    o.z = di * fmaxf(fmaf(di, a.z, bb.z), 0.f);
    o.w = di * fmaxf(fmaf(di, a.w, bb.w), 0.f);
    g_p2[node * 4 + c] = o;
}

// ---------------------------------------------------------------------------
// 7) Layer-2 aggregation (gather): accB = p2[self] + sum p2[neighbors]
// ---------------------------------------------------------------------------
__global__ __launch_bounds__(256) void k_agg2(int n) {
    int t = blockIdx.x * blockDim.x + threadIdx.x;
    int node = t >> 2;
    if (node >= n) return;
    int c = t & 3;

    int st  = g_start[node];
    int cnt = g_deg[node] - 1;
    float4 a = g_p2[node * 4 + c];

    int j = 0;
    for (; j + 4 <= cnt; j += 4) {
        int s0 = __ldg(&g_csr[st + j]);
        int s1 = __ldg(&g_csr[st + j + 1]);
        int s2 = __ldg(&g_csr[st + j + 2]);
        int s3 = __ldg(&g_csr[st + j + 3]);
        float4 v0 = __ldg(&g_p2[s0 * 4 + c]);
        float4 v1 = __ldg(&g_p2[s1 * 4 + c]);
        float4 v2 = __ldg(&g_p2[s2 * 4 + c]);
        float4 v3 = __ldg(&g_p2[s3 * 4 + c]);
        a.x += v0.x + v1.x + v2.x + v3.x;
        a.y += v0.y + v1.y + v2.y + v3.y;
        a.z += v0.z + v1.z + v2.z + v3.z;
        a.w += v0.w + v1.w + v2.w + v3.w;
    }
    for (; j < cnt; j++) {
        int s = __ldg(&g_csr[st + j]);
        float4 v = __ldg(&g_p2[s * 4 + c]);
        a.x += v.x; a.y += v.y; a.z += v.z; a.w += v.w;
    }

    g_accB[node * 4 + c] = a;
}

// ---------------------------------------------------------------------------
// 8) Fused layer-2 GEMM (@W2 + b2 + relu) + global mean pool.
//    Warp = one node/iter; lane = output feature; shfl-broadcast input row.
//    batch sorted -> register accumulation per graph, flush on change.
// ---------------------------------------------------------------------------
__global__ __launch_bounds__(256) void k_pool(const int* __restrict__ batch,
                                              const float* __restrict__ W2,
                                              const float* __restrict__ b2,
                                              int n) {
    __shared__ float W2s[512];  // 16x32
    int tid = threadIdx.x;
    #pragma unroll
    for (int i = tid; i < 512; i += 256) W2s[i] = W2[i];
    __syncthreads();

    int lane = tid & 31;
    int sub  = tid >> 5;
    int base = blockIdx.x * 256;
    float bb = __ldg(&b2[lane]);
    const float* accB = (const float*)g_accB;

    int cur = -1;
    float rsum = 0.f, rcnt = 0.f;

    for (int it = 0; it < 32; it++) {
        int i = base + it * 8 + sub;
        if (i < n) {
            int g = batch[i];
            if (g != cur) {
                if (cur >= 0) {
                    atomicAdd(&g_pool[cur * 32 + lane], rsum);
                    if (lane == 0) atomicAdd(&g_cnt[cur], rcnt);
                }
                cur = g; rsum = 0.f; rcnt = 0.f;
            }
            float di  = g_dinv[i];
            float myv = 0.f;
            if (lane < 16) myv = accB[(size_t)i * 16 + lane] * di;
            float acc = bb;
            #pragma unroll
            for (int k = 0; k < 16; k++) {
                float vk = __shfl_sync(0xffffffffu, myv, k);
                acc = fmaf(vk, W2s[k * 32 + lane], acc);
            }
            rsum += fmaxf(acc, 0.f);
            rcnt += 1.f;
        }
    }
    if (cur >= 0) {
        atomicAdd(&g_pool[cur * 32 + lane], rsum);
        if (lane == 0) atomicAdd(&g_cnt[cur], rcnt);
    }
}

// ---------------------------------------------------------------------------
// 9) MLP head: g=[64,32] mean -> relu(g@Wf1+bf1) -> @Wf2+bf2 -> out [64,8]
// ---------------------------------------------------------------------------
__global__ __launch_bounds__(64) void k_mlp(const float* __restrict__ Wf1,
                                            const float* __restrict__ bf1,
                                            const float* __restrict__ Wf2,
                                            const float* __restrict__ bf2,
                                            float* __restrict__ out) {
    int g = threadIdx.x;
    if (g >= N_GRAPHS) return;

    float inv = 1.0f / fmaxf(g_cnt[g], 1.0f);
    float gv[32];
    #pragma unroll
    for (int c = 0; c < 32; c++) gv[c] = g_pool[g * 32 + c] * inv;

    float h[64];
    #pragma unroll 8
    for (int j = 0; j < 64; j++) {
        float s = __ldg(&bf1[j]);
        #pragma unroll
        for (int c = 0; c < 32; c++) s = fmaf(gv[c], __ldg(&Wf1[c * 64 + j]), s);
        h[j] = fmaxf(s, 0.f);
    }

    #pragma unroll
    for (int o = 0; o < 8; o++) {
        float s = __ldg(&bf2[o]);
        #pragma unroll 16
        for (int j = 0; j < 64; j++) s = fmaf(h[j], __ldg(&Wf2[j * 8 + o]), s);
        out[g * 8 + o] = s;
    }
}

// ---------------------------------------------------------------------------
// Launch
// ---------------------------------------------------------------------------
extern "C" void kernel_launch(void* const* d_in, const int* in_sizes, int n_in,
                              void* d_out, int out_size) {
    const float* x     = (const float*)d_in[0];
    const int*   ei    = (const int*)  d_in[1];
    const int*   batch = (const int*)  d_in[2];
    const float* W1    = (const float*)d_in[3];
    const float* b1    = (const float*)d_in[4];
    const float* W2    = (const float*)d_in[5];
    const float* b2    = (const float*)d_in[6];
    const float* Wf1   = (const float*)d_in[7];
    const float* bf1   = (const float*)d_in[8];
    const float* Wf2   = (const float*)d_in[9];
    const float* bf2   = (const float*)d_in[10];
    float* out = (float*)d_out;

    int N = in_sizes[0] / 128;
    int E = in_sizes[1] / 2;
    const int* src = ei;
    const int* dst = ei + E;

    k_init<<<CDIV(N, 256), 256>>>(N);
    k_deg<<<CDIV(E, 256), 256>>>(dst, E);
    k_dinv<<<CDIV(N, 256), 256>>>(N);
    k_alloc<<<CDIV(N, 256), 256>>>(N);
    k_place<<<CDIV(E, 256), 256>>>(src, dst, E);

    k_gemm1<<<CDIV(N, 256), 256>>>(x, W1, N);
    k_agg1<<<CDIV(N * 4, 256), 256>>>(b1, N);
    k_agg2<<<CDIV(N * 4, 256), 256>>>(N);

    k_pool<<<CDIV(N, 256), 256>>>(batch, W2, b2, N);
    k_mlp<<<1, 64>>>(Wf1, bf1, Wf2, bf2, out);
}

// round 5
// speedup vs baseline: 1.2115x; 1.0003x over previous
#include <cuda_runtime.h>

#define N_NODES_MAX 100000
#define N_GRAPHS    64
#define CAP         96          // ELL slots per node (indegree Poisson(32))
#define SPILL_MAX   8192

#define CDIV(a, b) (((a) + (b) - 1) / (b))

// ---------------------------------------------------------------------------
// Scratch (static device globals; no allocation allowed)
// ---------------------------------------------------------------------------
__device__ int    g_cur[N_NODES_MAX];           // fill cursor -> indegree
__device__ float  g_dinv[N_NODES_MAX];
__device__ int    g_ell[N_NODES_MAX * CAP];     // src ids grouped by dst (38.4MB)
__device__ int2   g_spill[SPILL_MAX];           // (dst, src) overflow edges
__device__ int    g_spn;                        // spill count
__device__ float4 g_hs1[N_NODES_MAX * 4];       // RAW layer1 features [N,16]
__device__ float4 g_p2[N_NODES_MAX * 4];        // dinv-prescaled layer2 input
__device__ float4 g_accB[N_NODES_MAX * 4];      // layer2 aggregate (16 feats)
__device__ float  g_pool[N_GRAPHS * 32];
__device__ float  g_cnt[N_GRAPHS];

// ---------------------------------------------------------------------------
// 1) init: zero ELL cursors
// ---------------------------------------------------------------------------
__global__ void k_init(int n) {
    int i = blockIdx.x * blockDim.x + threadIdx.x;
    if (i < n) g_cur[i] = 0;
}

// 3) init2: zero pool / cnt / spill counter (tiny)
__global__ void k_init2() {
    int i = blockIdx.x * blockDim.x + threadIdx.x;
    if (i < N_GRAPHS * 32) g_pool[i] = 0.0f;
    if (i < N_GRAPHS)      g_cnt[i]  = 0.0f;
    if (i == 0)            g_spn = 0;
}

// ---------------------------------------------------------------------------
// 2) GEMM1: hs1_raw = x @ W1  [N,128]x[128,16]  (no dinv — independent of graph)
//    256 threads, 256 rows/block; balanced LDS vs FMA; XOR-swizzled xs.
// ---------------------------------------------------------------------------
__global__ __launch_bounds__(256, 4) void k_gemm1(const float* __restrict__ x,
                                                  const float* __restrict__ W1,
                                                  int n) {
    __shared__ float4 xs[8 * 256];  // [c][row^c] 32KB
    __shared__ float4 Ws[512];      // W1: 128x16 floats = 8KB

    int tid  = threadIdx.x;
    int base = blockIdx.x * 256;
    int rg = tid >> 2;   // 0..63
    int jg = tid & 3;    // output f4 0..3

    const float4* W4 = (const float4*)W1;
    Ws[tid]       = W4[tid];
    Ws[tid + 256] = W4[tid + 256];

    const float4* x4 = (const float4*)x;
    float4 acc[4];
    #pragma unroll
    for (int rr = 0; rr < 4; rr++) acc[rr] = make_float4(0.f, 0.f, 0.f, 0.f);

    #pragma unroll
    for (int chunk = 0; chunk < 4; chunk++) {
        __syncthreads();
        #pragma unroll
        for (int m = 0; m < 8; m++) {
            int i   = m * 256 + tid;
            int row = i >> 3, c = i & 7;
            float4 v = make_float4(0.f, 0.f, 0.f, 0.f);
            if (base + row < n) v = x4[(size_t)(base + row) * 32 + chunk * 8 + c];
            xs[c * 256 + (row ^ c)] = v;
        }
        __syncthreads();

        #pragma unroll
        for (int c4 = 0; c4 < 8; c4++) {
            float4 xv[4];
            #pragma unroll
            for (int rr = 0; rr < 4; rr++)
                xv[rr] = xs[c4 * 256 + ((rr * 64 + rg) ^ c4)];
            #pragma unroll
            for (int kk = 0; kk < 4; kk++) {
                float4 w = Ws[(chunk * 32 + c4 * 4 + kk) * 4 + jg];
                #pragma unroll
                for (int rr = 0; rr < 4; rr++) {
                    float e = (kk == 0) ? xv[rr].x : (kk == 1) ? xv[rr].y
                            : (kk == 2) ? xv[rr].z : xv[rr].w;
                    acc[rr].x = fmaf(e, w.x, acc[rr].x);
                    acc[rr].y = fmaf(e, w.y, acc[rr].y);
                    acc[rr].z = fmaf(e, w.z, acc[rr].z);
                    acc[rr].w = fmaf(e, w.w, acc[rr].w);
                }
            }
        }
    }

    #pragma unroll
    for (int rr = 0; rr < 4; rr++) {
        int r = base + rr * 64 + rg;
        if (r < n) g_hs1[r * 4 + jg] = acc[rr];
    }
}

// ---------------------------------------------------------------------------
// 4) ELL placement (single E-pass; cur becomes indegree)
// ---------------------------------------------------------------------------
__global__ void k_place(const int* __restrict__ src,
                        const int* __restrict__ dst, int E) {
    int e = blockIdx.x * blockDim.x + threadIdx.x;
    if (e >= E) return;
    int d = __ldg(&dst[e]);
    int s = __ldg(&src[e]);
    int pos = atomicAdd(&g_cur[d], 1);
    if (pos < CAP) {
        g_ell[d * CAP + pos] = s;
    } else {
        int sp = atomicAdd(&g_spn, 1);
        if (sp < SPILL_MAX) g_spill[sp] = make_int2(d, s);
    }
}

// 5) dinv = rsqrt(indegree + 1)   (+1 = self loop)
__global__ void k_dinv(int n) {
    int i = blockIdx.x * blockDim.x + threadIdx.x;
    if (i < n) g_dinv[i] = rsqrtf((float)(g_cur[i] + 1));
}

// ---------------------------------------------------------------------------
// 6) Layer-1 aggregation (gather) + fused epilogue.
//    4 threads/node (c = t&3). a = Σ dinv[s]·hs1raw[s] over self+neighbors;
//    p2 = dinv · relu(dinv·a + b1)  (prescaled for layer 2).
// ---------------------------------------------------------------------------
__global__ __launch_bounds__(256) void k_agg1(const float* __restrict__ b1, int n) {
    int t = blockIdx.x * blockDim.x + threadIdx.x;
    int node = t >> 2;
    if (node >= n) return;
    int c = t & 3;

    int cnt  = g_cur[node];
    int m    = min(cnt, CAP);
    int base = node * CAP;
    float din = g_dinv[node];

    float4 a = g_hs1[node * 4 + c];           // self (raw)
    a.x *= din; a.y *= din; a.z *= din; a.w *= din;

    int j = 0;
    for (; j + 4 <= m; j += 4) {
        int s0 = __ldg(&g_ell[base + j]);
        int s1 = __ldg(&g_ell[base + j + 1]);
        int s2 = __ldg(&g_ell[base + j + 2]);
        int s3 = __ldg(&g_ell[base + j + 3]);
        float d0 = __ldg(&g_dinv[s0]), d1 = __ldg(&g_dinv[s1]);
        float d2 = __ldg(&g_dinv[s2]), d3 = __ldg(&g_dinv[s3]);
        float4 v0 = __ldg(&g_hs1[s0 * 4 + c]);
        float4 v1 = __ldg(&g_hs1[s1 * 4 + c]);
        float4 v2 = __ldg(&g_hs1[s2 * 4 + c]);
        float4 v3 = __ldg(&g_hs1[s3 * 4 + c]);
        a.x += d0 * v0.x + d1 * v1.x + d2 * v2.x + d3 * v3.x;
        a.y += d0 * v0.y + d1 * v1.y + d2 * v2.y + d3 * v3.y;
        a.z += d0 * v0.z + d1 * v1.z + d2 * v2.z + d3 * v3.z;
        a.w += d0 * v0.w + d1 * v1.w + d2 * v2.w + d3 * v3.w;
    }
    for (; j < m; j++) {
        int s = __ldg(&g_ell[base + j]);
        float ds = __ldg(&g_dinv[s]);
        float4 v = __ldg(&g_hs1[s * 4 + c]);
        a.x += ds * v.x; a.y += ds * v.y; a.z += ds * v.z; a.w += ds * v.w;
    }
    if (cnt > CAP) {  // exceedingly rare: scan spill list
        int spn = min(g_spn, SPILL_MAX);
        for (int k = 0; k < spn; k++) {
            int2 e = g_spill[k];
            if (e.x == node) {
                float ds = g_dinv[e.y];
                float4 v = g_hs1[e.y * 4 + c];
                a.x += ds * v.x; a.y += ds * v.y; a.z += ds * v.z; a.w += ds * v.w;
            }
        }
    }

    float4 bb = __ldg(&((const float4*)b1)[c]);
    float4 o;
    o.x = din * fmaxf(fmaf(din, a.x, bb.x), 0.f);
    o.y = din * fmaxf(fmaf(din, a.y, bb.y), 0.f);
    o.z = din * fmaxf(fmaf(din, a.z, bb.z), 0.f);
    o.w = din * fmaxf(fmaf(din, a.w, bb.w), 0.f);
    g_p2[node * 4 + c] = o;
}

// ---------------------------------------------------------------------------
// 7) Layer-2 aggregation: accB = p2[self] + Σ p2[neighbors] (p2 prescaled)
// ---------------------------------------------------------------------------
__global__ __launch_bounds__(256) void k_agg2(int n) {
    int t = blockIdx.x * blockDim.x + threadIdx.x;
    int node = t >> 2;
    if (node >= n) return;
    int c = t & 3;

    int cnt  = g_cur[node];
    int m    = min(cnt, CAP);
    int base = node * CAP;
    float4 a = g_p2[node * 4 + c];

    int j = 0;
    for (; j + 4 <= m; j += 4) {
        int s0 = __ldg(&g_ell[base + j]);
        int s1 = __ldg(&g_ell[base + j + 1]);
        int s2 = __ldg(&g_ell[base + j + 2]);
        int s3 = __ldg(&g_ell[base + j + 3]);
        float4 v0 = __ldg(&g_p2[s0 * 4 + c]);
        float4 v1 = __ldg(&g_p2[s1 * 4 + c]);
        float4 v2 = __ldg(&g_p2[s2 * 4 + c]);
        float4 v3 = __ldg(&g_p2[s3 * 4 + c]);
        a.x += v0.x + v1.x + v2.x + v3.x;
        a.y += v0.y + v1.y + v2.y + v3.y;
        a.z += v0.z + v1.z + v2.z + v3.z;
        a.w += v0.w + v1.w + v2.w + v3.w;
    }
    for (; j < m; j++) {
        int s = __ldg(&g_ell[base + j]);
        float4 v = __ldg(&g_p2[s * 4 + c]);
        a.x += v.x; a.y += v.y; a.z += v.z; a.w += v.w;
    }
    if (cnt > CAP) {
        int spn = min(g_spn, SPILL_MAX);
        for (int k = 0; k < spn; k++) {
            int2 e = g_spill[k];
            if (e.x == node) {
                float4 v = g_p2[e.y * 4 + c];
                a.x += v.x; a.y += v.y; a.z += v.z; a.w += v.w;
            }
        }
    }

    g_accB[node * 4 + c] = a;
}

// ---------------------------------------------------------------------------
// 8) Fused layer-2 GEMM (@W2 + b2 + relu) + global mean pool.
// ---------------------------------------------------------------------------
__global__ __launch_bounds__(256) void k_pool(const int* __restrict__ batch,
                                              const float* __restrict__ W2,
                                              const float* __restrict__ b2,
                                              int n) {
    __shared__ float W2s[512];  // 16x32
    int tid = threadIdx.x;
    #pragma unroll
    for (int i = tid; i < 512; i += 256) W2s[i] = W2[i];
    __syncthreads();

    int lane = tid & 31;
    int sub  = tid >> 5;
    int base = blockIdx.x * 256;
    float bb = __ldg(&b2[lane]);
    const float* accB = (const float*)g_accB;

    int cur = -1;
    float rsum = 0.f, rcnt = 0.f;

    for (int it = 0; it < 32; it++) {
        int i = base + it * 8 + sub;
        if (i < n) {
            int g = batch[i];
            if (g != cur) {
                if (cur >= 0) {
                    atomicAdd(&g_pool[cur * 32 + lane], rsum);
                    if (lane == 0) atomicAdd(&g_cnt[cur], rcnt);
                }
                cur = g; rsum = 0.f; rcnt = 0.f;
            }
            float di  = g_dinv[i];
            float myv = 0.f;
            if (lane < 16) myv = accB[(size_t)i * 16 + lane] * di;
            float acc = bb;
            #pragma unroll
            for (int k = 0; k < 16; k++) {
                float vk = __shfl_sync(0xffffffffu, myv, k);
                acc = fmaf(vk, W2s[k * 32 + lane], acc);
            }
            rsum += fmaxf(acc, 0.f);
            rcnt += 1.f;
        }
    }
    if (cur >= 0) {
        atomicAdd(&g_pool[cur * 32 + lane], rsum);
        if (lane == 0) atomicAdd(&g_cnt[cur], rcnt);
    }
}

// ---------------------------------------------------------------------------
// 9) MLP head
// ---------------------------------------------------------------------------
__global__ __launch_bounds__(64) void k_mlp(const float* __restrict__ Wf1,
                                            const float* __restrict__ bf1,
                                            const float* __restrict__ Wf2,
                                            const float* __restrict__ bf2,
                                            float* __restrict__ out) {
    int g = threadIdx.x;
    if (g >= N_GRAPHS) return;

    float inv = 1.0f / fmaxf(g_cnt[g], 1.0f);
    float gv[32];
    #pragma unroll
    for (int c = 0; c < 32; c++) gv[c] = g_pool[g * 32 + c] * inv;

    float h[64];
    #pragma unroll 8
    for (int j = 0; j < 64; j++) {
        float s = __ldg(&bf1[j]);
        #pragma unroll
        for (int c = 0; c < 32; c++) s = fmaf(gv[c], __ldg(&Wf1[c * 64 + j]), s);
        h[j] = fmaxf(s, 0.f);
    }

    #pragma unroll
    for (int o = 0; o < 8; o++) {
        float s = __ldg(&bf2[o]);
        #pragma unroll 16
        for (int j = 0; j < 64; j++) s = fmaf(h[j], __ldg(&Wf2[j * 8 + o]), s);
        out[g * 8 + o] = s;
    }
}

// ---------------------------------------------------------------------------
// Launch (k_place intentionally at slot 4 -> gets the ncu profile next round)
// ---------------------------------------------------------------------------
extern "C" void kernel_launch(void* const* d_in, const int* in_sizes, int n_in,
                              void* d_out, int out_size) {
    const float* x     = (const float*)d_in[0];
    const int*   ei    = (const int*)  d_in[1];
    const int*   batch = (const int*)  d_in[2];
    const float* W1    = (const float*)d_in[3];
    const float* b1    = (const float*)d_in[4];
    const float* W2    = (const float*)d_in[5];
    const float* b2    = (const float*)d_in[6];
    const float* Wf1   = (const float*)d_in[7];
    const float* bf1   = (const float*)d_in[8];
    const float* Wf2   = (const float*)d_in[9];
    const float* bf2   = (const float*)d_in[10];
    float* out = (float*)d_out;

    int N = in_sizes[0] / 128;
    int E = in_sizes[1] / 2;
    const int* src = ei;
    const int* dst = ei + E;

    k_init <<<CDIV(N, 256), 256>>>(N);          // 1
    k_gemm1<<<CDIV(N, 256), 256>>>(x, W1, N);   // 2 (graph-independent)
    k_init2<<<8, 256>>>();                      // 3
    k_place<<<CDIV(E, 256), 256>>>(src, dst, E);// 4  <- profiled
    k_dinv <<<CDIV(N, 256), 256>>>(N);          // 5
    k_agg1 <<<CDIV(N * 4, 256), 256>>>(b1, N);  // 6
    k_agg2 <<<CDIV(N * 4, 256), 256>>>(N);      // 7
    k_pool <<<CDIV(N, 256), 256>>>(batch, W2, b2, N); // 8
    k_mlp  <<<1, 64>>>(Wf1, bf1, Wf2, bf2, out);      // 9
}

// round 7
// speedup vs baseline: 1.2978x; 1.0713x over previous
#include <cuda_runtime.h>

#define N_NODES_MAX 100000
#define N_GRAPHS    64
#define CAP         96          // ELL slots per node (indegree Poisson(32))
#define SPILL_MAX   8192

#define CDIV(a, b) (((a) + (b) - 1) / (b))

// ---------------------------------------------------------------------------
// Scratch (static device globals; no allocation allowed)
// ---------------------------------------------------------------------------
__device__ int    g_cur[N_NODES_MAX];           // fill cursor -> indegree
__device__ float  g_dinv[N_NODES_MAX];
__device__ int    g_ell[N_NODES_MAX * CAP];     // src ids grouped by dst
__device__ int2   g_spill[SPILL_MAX];           // (dst, src) overflow edges
__device__ int    g_spn;                        // spill count
__device__ float4 g_hs1[N_NODES_MAX * 4];       // dinv-PRESCALED layer1 feats [N,16]
__device__ float4 g_p2[N_NODES_MAX * 4];        // dinv-prescaled layer2 input
__device__ float4 g_accB[N_NODES_MAX * 4];      // layer2 aggregate (16 feats)
__device__ float  g_pool[N_GRAPHS * 32];
__device__ float  g_cnt[N_GRAPHS];

// ---------------------------------------------------------------------------
// 1) init: zero cursors, pool, cnt, spill counter
// ---------------------------------------------------------------------------
__global__ void k_init(int n) {
    int i = blockIdx.x * blockDim.x + threadIdx.x;
    if (i < n)             g_cur[i] = 0;
    if (i < N_GRAPHS * 32) g_pool[i] = 0.0f;
    if (i < N_GRAPHS)      g_cnt[i]  = 0.0f;
    if (i == 0)            g_spn = 0;
}

// ---------------------------------------------------------------------------
// 2) ELL placement, 4 edges/thread (int4 loads, MLP=4 on the atomic chains)
// ---------------------------------------------------------------------------
__device__ __forceinline__ void place_one(int d, int s) {
    int pos = atomicAdd(&g_cur[d], 1);
    if (pos < CAP) {
        g_ell[d * CAP + pos] = s;
    } else {
        int sp = atomicAdd(&g_spn, 1);
        if (sp < SPILL_MAX) g_spill[sp] = make_int2(d, s);
    }
}

__global__ void k_place4(const int4* __restrict__ src4,
                         const int4* __restrict__ dst4, int E4) {
    int t = blockIdx.x * blockDim.x + threadIdx.x;
    if (t >= E4) return;
    int4 s = __ldg(&src4[t]);
    int4 d = __ldg(&dst4[t]);
    place_one(d.x, s.x);
    place_one(d.y, s.y);
    place_one(d.z, s.z);
    place_one(d.w, s.w);
}

__global__ void k_place_tail(const int* __restrict__ src,
                             const int* __restrict__ dst, int lo, int E) {
    int e = lo + blockIdx.x * blockDim.x + threadIdx.x;
    if (e >= E) return;
    place_one(__ldg(&dst[e]), __ldg(&src[e]));
}

// ---------------------------------------------------------------------------
// 3) GEMM1 (+fused dinv): hs1 = dinv * (x @ W1), dinv = rsqrt(indeg+1).
//    Runs AFTER place so g_cur holds the final indegree.
//    256 threads, 256 rows/block; balanced LDS/FMA; XOR-swizzled xs.
// ---------------------------------------------------------------------------
__global__ __launch_bounds__(256, 4) void k_gemm1(const float* __restrict__ x,
                                                  const float* __restrict__ W1,
                                                  int n) {
    __shared__ float4 xs[8 * 256];  // [c][row^c] 32KB
    __shared__ float4 Ws[512];      // W1: 128x16 floats = 8KB

    int tid  = threadIdx.x;
    int base = blockIdx.x * 256;
    int rg = tid >> 2;   // 0..63
    int jg = tid & 3;    // output f4 0..3

    const float4* W4 = (const float4*)W1;
    Ws[tid]       = W4[tid];
    Ws[tid + 256] = W4[tid + 256];

    const float4* x4 = (const float4*)x;
    float4 acc[4];
    #pragma unroll
    for (int rr = 0; rr < 4; rr++) acc[rr] = make_float4(0.f, 0.f, 0.f, 0.f);

    #pragma unroll
    for (int chunk = 0; chunk < 4; chunk++) {
        __syncthreads();
        #pragma unroll
        for (int m = 0; m < 8; m++) {
            int i   = m * 256 + tid;
            int row = i >> 3, c = i & 7;
            float4 v = make_float4(0.f, 0.f, 0.f, 0.f);
            if (base + row < n) v = x4[(size_t)(base + row) * 32 + chunk * 8 + c];
            xs[c * 256 + (row ^ c)] = v;
        }
        __syncthreads();

        #pragma unroll
        for (int c4 = 0; c4 < 8; c4++) {
            float4 xv[4];
            #pragma unroll
            for (int rr = 0; rr < 4; rr++)
                xv[rr] = xs[c4 * 256 + ((rr * 64 + rg) ^ c4)];
            #pragma unroll
            for (int kk = 0; kk < 4; kk++) {
                float4 w = Ws[(chunk * 32 + c4 * 4 + kk) * 4 + jg];
                #pragma unroll
                for (int rr = 0; rr < 4; rr++) {
                    float e = (kk == 0) ? xv[rr].x : (kk == 1) ? xv[rr].y
                            : (kk == 2) ? xv[rr].z : xv[rr].w;
                    acc[rr].x = fmaf(e, w.x, acc[rr].x);
                    acc[rr].y = fmaf(e, w.y, acc[rr].y);
                    acc[rr].z = fmaf(e, w.z, acc[rr].z);
                    acc[rr].w = fmaf(e, w.w, acc[rr].w);
                }
            }
        }
    }

    #pragma unroll
    for (int rr = 0; rr < 4; rr++) {
        int r = base + rr * 64 + rg;
        if (r < n) {
            float din = rsqrtf((float)(g_cur[r] + 1));
            if (jg == 0) g_dinv[r] = din;
            g_hs1[r * 4 + jg] = make_float4(acc[rr].x * din, acc[rr].y * din,
                                            acc[rr].z * din, acc[rr].w * din);
        }
    }
}

// ---------------------------------------------------------------------------
// 4) Layer-1 aggregation + fused epilogue.
//    4 lanes/node (c = t&3). Lanes cooperatively load 4 consecutive ELL
//    indices and shfl(width=4)-share them; unroll 8 -> 8 independent
//    feature loads in flight. a = Σ hs1[s] (prescaled) over self+neighbors;
//    p2 = dinv · relu(dinv·a + b1).
// ---------------------------------------------------------------------------
__global__ __launch_bounds__(256) void k_agg1(const float* __restrict__ b1, int n) {
    int t = blockIdx.x * blockDim.x + threadIdx.x;
    int node = t >> 2;
    bool valid = node < n;
    if (node >= n) node = n - 1;    // keep all lanes active for shfl
    int c = t & 3;

    int cnt  = g_cur[node];
    int m    = min(cnt, CAP);
    int base = node * CAP;

    float4 a = g_hs1[node * 4 + c];   // self (prescaled)

    int j = 0;
    for (; j + 8 <= m; j += 8) {
        int i0 = __ldg(&g_ell[base + j + c]);
        int i1 = __ldg(&g_ell[base + j + 4 + c]);
        int s0 = __shfl_sync(0xffffffffu, i0, 0, 4);
        int s1 = __shfl_sync(0xffffffffu, i0, 1, 4);
        int s2 = __shfl_sync(0xffffffffu, i0, 2, 4);
        int s3 = __shfl_sync(0xffffffffu, i0, 3, 4);
        int s4 = __shfl_sync(0xffffffffu, i1, 0, 4);
        int s5 = __shfl_sync(0xffffffffu, i1, 1, 4);
        int s6 = __shfl_sync(0xffffffffu, i1, 2, 4);
        int s7 = __shfl_sync(0xffffffffu, i1, 3, 4);
        float4 v0 = __ldg(&g_hs1[s0 * 4 + c]);
        float4 v1 = __ldg(&g_hs1[s1 * 4 + c]);
        float4 v2 = __ldg(&g_hs1[s2 * 4 + c]);
        float4 v3 = __ldg(&g_hs1[s3 * 4 + c]);
        float4 v4 = __ldg(&g_hs1[s4 * 4 + c]);
        float4 v5 = __ldg(&g_hs1[s5 * 4 + c]);
        float4 v6 = __ldg(&g_hs1[s6 * 4 + c]);
        float4 v7 = __ldg(&g_hs1[s7 * 4 + c]);
        a.x += ((v0.x + v1.x) + (v2.x + v3.x)) + ((v4.x + v5.x) + (v6.x + v7.x));
        a.y += ((v0.y + v1.y) + (v2.y + v3.y)) + ((v4.y + v5.y) + (v6.y + v7.y));
        a.z += ((v0.z + v1.z) + (v2.z + v3.z)) + ((v4.z + v5.z) + (v6.z + v7.z));
        a.w += ((v0.w + v1.w) + (v2.w + v3.w)) + ((v4.w + v5.w) + (v6.w + v7.w));
    }
    for (; j < m; j++) {
        int s = __ldg(&g_ell[base + j]);
        float4 v = __ldg(&g_hs1[s * 4 + c]);
        a.x += v.x; a.y += v.y; a.z += v.z; a.w += v.w;
    }
    if (cnt > CAP) {
        int spn = min(g_spn, SPILL_MAX);
        for (int k = 0; k < spn; k++) {
            int2 e = g_spill[k];
            if (e.x == node) {
                float4 v = g_hs1[e.y * 4 + c];
                a.x += v.x; a.y += v.y; a.z += v.z; a.w += v.w;
            }
        }
    }

    if (valid) {
        float din = g_dinv[node];
        float4 bb = __ldg(&((const float4*)b1)[c]);
        float4 o;
        o.x = din * fmaxf(fmaf(din, a.x, bb.x), 0.f);
        o.y = din * fmaxf(fmaf(din, a.y, bb.y), 0.f);
        o.z = din * fmaxf(fmaf(din, a.z, bb.z), 0.f);
        o.w = din * fmaxf(fmaf(din, a.w, bb.w), 0.f);
        g_p2[node * 4 + c] = o;
    }
}

// ---------------------------------------------------------------------------
// 5) Layer-2 aggregation: accB = p2[self] + Σ p2[neighbors]
// ---------------------------------------------------------------------------
__global__ __launch_bounds__(256) void k_agg2(int n) {
    int t = blockIdx.x * blockDim.x + threadIdx.x;
    int node = t >> 2;
    bool valid = node < n;
    if (node >= n) node = n - 1;
    int c = t & 3;

    int cnt  = g_cur[node];
    int m    = min(cnt, CAP);
    int base = node * CAP;
    float4 a = g_p2[node * 4 + c];

    int j = 0;
    for (; j + 8 <= m; j += 8) {
        int i0 = __ldg(&g_ell[base + j + c]);
        int i1 = __ldg(&g_ell[base + j + 4 + c]);
        int s0 = __shfl_sync(0xffffffffu, i0, 0, 4);
        int s1 = __shfl_sync(0xffffffffu, i0, 1, 4);
        int s2 = __shfl_sync(0xffffffffu, i0, 2, 4);
        int s3 = __shfl_sync(0xffffffffu, i0, 3, 4);
        int s4 = __shfl_sync(0xffffffffu, i1, 0, 4);
        int s5 = __shfl_sync(0xffffffffu, i1, 1, 4);
        int s6 = __shfl_sync(0xffffffffu, i1, 2, 4);
        int s7 = __shfl_sync(0xffffffffu, i1, 3, 4);
        float4 v0 = __ldg(&g_p2[s0 * 4 + c]);
        float4 v1 = __ldg(&g_p2[s1 * 4 + c]);
        float4 v2 = __ldg(&g_p2[s2 * 4 + c]);
        float4 v3 = __ldg(&g_p2[s3 * 4 + c]);
        float4 v4 = __ldg(&g_p2[s4 * 4 + c]);
        float4 v5 = __ldg(&g_p2[s5 * 4 + c]);
        float4 v6 = __ldg(&g_p2[s6 * 4 + c]);
        float4 v7 = __ldg(&g_p2[s7 * 4 + c]);
        a.x += ((v0.x + v1.x) + (v2.x + v3.x)) + ((v4.x + v5.x) + (v6.x + v7.x));
        a.y += ((v0.y + v1.y) + (v2.y + v3.y)) + ((v4.y + v5.y) + (v6.y + v7.y));
        a.z += ((v0.z + v1.z) + (v2.z + v3.z)) + ((v4.z + v5.z) + (v6.z + v7.z));
        a.w += ((v0.w + v1.w) + (v2.w + v3.w)) + ((v4.w + v5.w) + (v6.w + v7.w));
    }
    for (; j < m; j++) {
        int s = __ldg(&g_ell[base + j]);
        float4 v = __ldg(&g_p2[s * 4 + c]);
        a.x += v.x; a.y += v.y; a.z += v.z; a.w += v.w;
    }
    if (cnt > CAP) {
        int spn = min(g_spn, SPILL_MAX);
        for (int k = 0; k < spn; k++) {
            int2 e = g_spill[k];
            if (e.x == node) {
                float4 v = g_p2[e.y * 4 + c];
                a.x += v.x; a.y += v.y; a.z += v.z; a.w += v.w;
            }
        }
    }

    if (valid) g_accB[node * 4 + c] = a;
}

// ---------------------------------------------------------------------------
// 6) Fused layer-2 GEMM (@W2 + b2 + relu) + global mean pool.
// ---------------------------------------------------------------------------
__global__ __launch_bounds__(256) void k_pool(const int* __restrict__ batch,
                                              const float* __restrict__ W2,
                                              const float* __restrict__ b2,
                                              int n) {
    __shared__ float W2s[512];  // 16x32
    int tid = threadIdx.x;
    #pragma unroll
    for (int i = tid; i < 512; i += 256) W2s[i] = W2[i];
    __syncthreads();

    int lane = tid & 31;
    int sub  = tid >> 5;
    int base = blockIdx.x * 256;
    float bb = __ldg(&b2[lane]);
    const float* accB = (const float*)g_accB;

    int cur = -1;
    float rsum = 0.f, rcnt = 0.f;

    for (int it = 0; it < 32; it++) {
        int i = base + it * 8 + sub;
        if (i < n) {
            int g = batch[i];
            if (g != cur) {
                if (cur >= 0) {
                    atomicAdd(&g_pool[cur * 32 + lane], rsum);
                    if (lane == 0) atomicAdd(&g_cnt[cur], rcnt);
                }
                cur = g; rsum = 0.f; rcnt = 0.f;
            }
            float di  = g_dinv[i];
            float myv = 0.f;
            if (lane < 16) myv = accB[(size_t)i * 16 + lane] * di;
            float acc = bb;
            #pragma unroll
            for (int k = 0; k < 16; k++) {
                float vk = __shfl_sync(0xffffffffu, myv, k);
                acc = fmaf(vk, W2s[k * 32 + lane], acc);
            }
            rsum += fmaxf(acc, 0.f);
            rcnt += 1.f;
        }
    }
    if (cur >= 0) {
        atomicAdd(&g_pool[cur * 32 + lane], rsum);
        if (lane == 0) atomicAdd(&g_cnt[cur], rcnt);
    }
}

// ---------------------------------------------------------------------------
// 7) MLP head
// ---------------------------------------------------------------------------
__global__ __launch_bounds__(64) void k_mlp(const float* __restrict__ Wf1,
                                            const float* __restrict__ bf1,
                                            const float* __restrict__ Wf2,
                                            const float* __restrict__ bf2,
                                            float* __restrict__ out) {
    int g = threadIdx.x;
    if (g >= N_GRAPHS) return;

    float inv = 1.0f / fmaxf(g_cnt[g], 1.0f);
    float gv[32];
    #pragma unroll
    for (int c = 0; c < 32; c++) gv[c] = g_pool[g * 32 + c] * inv;

    float h[64];
    #pragma unroll 8
    for (int j = 0; j < 64; j++) {
        float s = __ldg(&bf1[j]);
        #pragma unroll
        for (int c = 0; c < 32; c++) s = fmaf(gv[c], __ldg(&Wf1[c * 64 + j]), s);
        h[j] = fmaxf(s, 0.f);
    }

    #pragma unroll
    for (int o = 0; o < 8; o++) {
        float s = __ldg(&bf2[o]);
        #pragma unroll 16
        for (int j = 0; j < 64; j++) s = fmaf(h[j], __ldg(&Wf2[j * 8 + o]), s);
        out[g * 8 + o] = s;
    }
}

// ---------------------------------------------------------------------------
// Launch (k_agg1 at slot 4 -> gets the ncu profile next round)
// ---------------------------------------------------------------------------
extern "C" void kernel_launch(void* const* d_in, const int* in_sizes, int n_in,
                              void* d_out, int out_size) {
    const float* x     = (const float*)d_in[0];
    const int*   ei    = (const int*)  d_in[1];
    const int*   batch = (const int*)  d_in[2];
    const float* W1    = (const float*)d_in[3];
    const float* b1    = (const float*)d_in[4];
    const float* W2    = (const float*)d_in[5];
    const float* b2    = (const float*)d_in[6];
    const float* Wf1   = (const float*)d_in[7];
    const float* bf1   = (const float*)d_in[8];
    const float* Wf2   = (const float*)d_in[9];
    const float* bf2   = (const float*)d_in[10];
    float* out = (float*)d_out;

    int N = in_sizes[0] / 128;
    int E = in_sizes[1] / 2;
    const int* src = ei;
    const int* dst = ei + E;

    // int4 fast path requires E%4==0 AND 16B-aligned src/dst (dst = ei+E).
    bool v4ok = ((E & 3) == 0) &&
                ((((unsigned long long)src) & 15ull) == 0) &&
                ((((unsigned long long)dst) & 15ull) == 0);
    int E4 = v4ok ? (E >> 2) : 0;

    k_init<<<CDIV(N, 256), 256>>>(N);                               // 1
    if (E4 > 0)
        k_place4<<<CDIV(E4, 256), 256>>>((const int4*)src, (const int4*)dst, E4); // 2
    else
        k_place_tail<<<CDIV(E, 256), 256>>>(src, dst, 0, E);        // 2 (fallback)
    k_gemm1<<<CDIV(N, 256), 256>>>(x, W1, N);                       // 3
    k_agg1 <<<CDIV(N * 4, 256), 256>>>(b1, N);                      // 4 <- profiled
    k_agg2 <<<CDIV(N * 4, 256), 256>>>(N);                          // 5
    k_pool <<<CDIV(N, 256), 256>>>(batch, W2, b2, N);               // 6
    k_mlp  <<<1, 64>>>(Wf1, bf1, Wf2, bf2, out);                    // 7
}

// round 8
// speedup vs baseline: 1.3673x; 1.0536x over previous
#include <cuda_runtime.h>

#define N_NODES_MAX 100000
#define N_GRAPHS    64
#define CAP         96          // ELL slots per node (indegree Poisson(32))
#define SPILL_MAX   8192

#define CDIV(a, b) (((a) + (b) - 1) / (b))

// ---------------------------------------------------------------------------
// Scratch (static device globals; no allocation allowed)
// ---------------------------------------------------------------------------
__device__ int    g_cur[N_NODES_MAX];           // fill cursor -> indegree
__device__ float  g_dinv[N_NODES_MAX];
__device__ int    g_ell[N_NODES_MAX * CAP];     // src ids grouped by dst
__device__ int2   g_spill[SPILL_MAX];           // (dst, src) overflow edges
__device__ int    g_spn;                        // spill count
__device__ float4 g_hs1[N_NODES_MAX * 4];       // dinv-PRESCALED layer1 feats [N,16]
__device__ float4 g_p2[N_NODES_MAX * 4];        // dinv-prescaled layer2 input
__device__ float4 g_accB[N_NODES_MAX * 4];      // layer2 aggregate (16 feats)
__device__ float  g_pool[N_GRAPHS * 32];
__device__ float  g_cnt[N_GRAPHS];

// ---------------------------------------------------------------------------
// 1) init: zero cursors, pool, cnt, spill counter
// ---------------------------------------------------------------------------
__global__ void k_init(int n) {
    int i = blockIdx.x * blockDim.x + threadIdx.x;
    if (i < n)             g_cur[i] = 0;
    if (i < N_GRAPHS * 32) g_pool[i] = 0.0f;
    if (i < N_GRAPHS)      g_cnt[i]  = 0.0f;
    if (i == 0)            g_spn = 0;
}

// ---------------------------------------------------------------------------
// 2) ELL placement, 4 edges/thread (int4 loads, MLP=4 on the atomic chains)
// ---------------------------------------------------------------------------
__device__ __forceinline__ void place_one(int d, int s) {
    int pos = atomicAdd(&g_cur[d], 1);
    if (pos < CAP) {
        g_ell[d * CAP + pos] = s;
    } else {
        int sp = atomicAdd(&g_spn, 1);
        if (sp < SPILL_MAX) g_spill[sp] = make_int2(d, s);
    }
}

__global__ void k_place4(const int4* __restrict__ src4,
                         const int4* __restrict__ dst4, int E4) {
    int t = blockIdx.x * blockDim.x + threadIdx.x;
    if (t >= E4) return;
    int4 s = __ldg(&src4[t]);
    int4 d = __ldg(&dst4[t]);
    place_one(d.x, s.x);
    place_one(d.y, s.y);
    place_one(d.z, s.z);
    place_one(d.w, s.w);
}

__global__ void k_place_tail(const int* __restrict__ src,
                             const int* __restrict__ dst, int lo, int E) {
    int e = lo + blockIdx.x * blockDim.x + threadIdx.x;
    if (e >= E) return;
    place_one(__ldg(&dst[e]), __ldg(&src[e]));
}

// ---------------------------------------------------------------------------
// 3) GEMM1 (+fused dinv): hs1 = dinv * (x @ W1), dinv = rsqrt(indeg+1).
//    Runs AFTER place so g_cur holds the final indegree.
// ---------------------------------------------------------------------------
__global__ __launch_bounds__(256, 4) void k_gemm1(const float* __restrict__ x,
                                                  const float* __restrict__ W1,
                                                  int n) {
    __shared__ float4 xs[8 * 256];  // [c][row^c] 32KB
    __shared__ float4 Ws[512];      // W1: 128x16 floats = 8KB

    int tid  = threadIdx.x;
    int base = blockIdx.x * 256;
    int rg = tid >> 2;   // 0..63
    int jg = tid & 3;    // output f4 0..3

    const float4* W4 = (const float4*)W1;
    Ws[tid]       = W4[tid];
    Ws[tid + 256] = W4[tid + 256];

    const float4* x4 = (const float4*)x;
    float4 acc[4];
    #pragma unroll
    for (int rr = 0; rr < 4; rr++) acc[rr] = make_float4(0.f, 0.f, 0.f, 0.f);

    #pragma unroll
    for (int chunk = 0; chunk < 4; chunk++) {
        __syncthreads();
        #pragma unroll
        for (int m = 0; m < 8; m++) {
            int i   = m * 256 + tid;
            int row = i >> 3, c = i & 7;
            float4 v = make_float4(0.f, 0.f, 0.f, 0.f);
            if (base + row < n) v = x4[(size_t)(base + row) * 32 + chunk * 8 + c];
            xs[c * 256 + (row ^ c)] = v;
        }
        __syncthreads();

        #pragma unroll
        for (int c4 = 0; c4 < 8; c4++) {
            float4 xv[4];
            #pragma unroll
            for (int rr = 0; rr < 4; rr++)
                xv[rr] = xs[c4 * 256 + ((rr * 64 + rg) ^ c4)];
            #pragma unroll
            for (int kk = 0; kk < 4; kk++) {
                float4 w = Ws[(chunk * 32 + c4 * 4 + kk) * 4 + jg];
                #pragma unroll
                for (int rr = 0; rr < 4; rr++) {
                    float e = (kk == 0) ? xv[rr].x : (kk == 1) ? xv[rr].y
                            : (kk == 2) ? xv[rr].z : xv[rr].w;
                    acc[rr].x = fmaf(e, w.x, acc[rr].x);
                    acc[rr].y = fmaf(e, w.y, acc[rr].y);
                    acc[rr].z = fmaf(e, w.z, acc[rr].z);
                    acc[rr].w = fmaf(e, w.w, acc[rr].w);
                }
            }
        }
    }

    #pragma unroll
    for (int rr = 0; rr < 4; rr++) {
        int r = base + rr * 64 + rg;
        if (r < n) {
            float din = rsqrtf((float)(g_cur[r] + 1));
            if (jg == 0) g_dinv[r] = din;
            g_hs1[r * 4 + jg] = make_float4(acc[rr].x * din, acc[rr].y * din,
                                            acc[rr].z * din, acc[rr].w * din);
        }
    }
}

// ---------------------------------------------------------------------------
// Warp-per-node aggregation core.
//    Lane l = (neighbor group l>>2, feature chunk l&3). Per round the warp
//    gathers 8 neighbors x 16B (full 32-lane LDG), unroll 2 -> 16/iter.
//    shfl_xor(4/8/16) reduces groups (preserves l&3); lanes 0-3 hold result.
// ---------------------------------------------------------------------------
__device__ __forceinline__ float4 agg_warp(const float4* __restrict__ feat,
                                           int node, int lane) {
    int grp = lane >> 2;
    int c   = lane & 3;
    int cnt  = g_cur[node];
    int m    = min(cnt, CAP);
    int base = node * CAP;

    float4 a = make_float4(0.f, 0.f, 0.f, 0.f);

    int j = 0;
    for (; j + 16 <= m; j += 16) {
        int s0 = __ldg(&g_ell[base + j + grp]);
        int s1 = __ldg(&g_ell[base + j + 8 + grp]);
        float4 v0 = __ldg(&feat[s0 * 4 + c]);
        float4 v1 = __ldg(&feat[s1 * 4 + c]);
        a.x += v0.x + v1.x; a.y += v0.y + v1.y;
        a.z += v0.z + v1.z; a.w += v0.w + v1.w;
    }
    for (; j < m; j += 8) {
        int jj = j + grp;
        if (jj < m) {
            int s = __ldg(&g_ell[base + jj]);
            float4 v = __ldg(&feat[s * 4 + c]);
            a.x += v.x; a.y += v.y; a.z += v.z; a.w += v.w;
        }
    }
    if (cnt > CAP && grp == 0) {   // rare overflow: lanes 0-3 scan spill list
        int spn = min(g_spn, SPILL_MAX);
        for (int k = 0; k < spn; k++) {
            int2 e = g_spill[k];
            if (e.x == node) {
                float4 v = feat[e.y * 4 + c];
                a.x += v.x; a.y += v.y; a.z += v.z; a.w += v.w;
            }
        }
    }

    #pragma unroll
    for (int off = 4; off < 32; off <<= 1) {
        a.x += __shfl_xor_sync(0xffffffffu, a.x, off);
        a.y += __shfl_xor_sync(0xffffffffu, a.y, off);
        a.z += __shfl_xor_sync(0xffffffffu, a.z, off);
        a.w += __shfl_xor_sync(0xffffffffu, a.w, off);
    }
    return a;   // valid in all lanes; lanes 0-3 use chunk c = lane
}

// 4) Layer-1 aggregation + epilogue: p2 = dinv * relu(dinv*(self+Σ) + b1)
__global__ __launch_bounds__(256) void k_agg1(const float* __restrict__ b1, int n) {
    int node = blockIdx.x * 8 + (threadIdx.x >> 5);
    if (node >= n) return;
    int lane = threadIdx.x & 31;

    float4 a = agg_warp(g_hs1, node, lane);

    if (lane < 4) {
        int c = lane;
        float4 self = g_hs1[node * 4 + c];
        a.x += self.x; a.y += self.y; a.z += self.z; a.w += self.w;
        float din = g_dinv[node];
        float4 bb = __ldg(&((const float4*)b1)[c]);
        float4 o;
        o.x = din * fmaxf(fmaf(din, a.x, bb.x), 0.f);
        o.y = din * fmaxf(fmaf(din, a.y, bb.y), 0.f);
        o.z = din * fmaxf(fmaf(din, a.z, bb.z), 0.f);
        o.w = din * fmaxf(fmaf(din, a.w, bb.w), 0.f);
        g_p2[node * 4 + c] = o;
    }
}

// 5) Layer-2 aggregation: accB = p2[self] + Σ p2[neighbors]
__global__ __launch_bounds__(256) void k_agg2(int n) {
    int node = blockIdx.x * 8 + (threadIdx.x >> 5);
    if (node >= n) return;
    int lane = threadIdx.x & 31;

    float4 a = agg_warp(g_p2, node, lane);

    if (lane < 4) {
        int c = lane;
        float4 self = g_p2[node * 4 + c];
        a.x += self.x; a.y += self.y; a.z += self.z; a.w += self.w;
        g_accB[node * 4 + c] = a;
    }
}

// ---------------------------------------------------------------------------
// 6) Fused layer-2 GEMM (@W2 + b2 + relu) + global mean pool.
// ---------------------------------------------------------------------------
__global__ __launch_bounds__(256) void k_pool(const int* __restrict__ batch,
                                              const float* __restrict__ W2,
                                              const float* __restrict__ b2,
                                              int n) {
    __shared__ float W2s[512];  // 16x32
    int tid = threadIdx.x;
    #pragma unroll
    for (int i = tid; i < 512; i += 256) W2s[i] = W2[i];
    __syncthreads();

    int lane = tid & 31;
    int sub  = tid >> 5;
    int base = blockIdx.x * 256;
    float bb = __ldg(&b2[lane]);
    const float* accB = (const float*)g_accB;

    int cur = -1;
    float rsum = 0.f, rcnt = 0.f;

    for (int it = 0; it < 32; it++) {
        int i = base + it * 8 + sub;
        if (i < n) {
            int g = batch[i];
            if (g != cur) {
                if (cur >= 0) {
                    atomicAdd(&g_pool[cur * 32 + lane], rsum);
                    if (lane == 0) atomicAdd(&g_cnt[cur], rcnt);
                }
                cur = g; rsum = 0.f; rcnt = 0.f;
            }
            float di  = g_dinv[i];
            float myv = 0.f;
            if (lane < 16) myv = accB[(size_t)i * 16 + lane] * di;
            float acc = bb;
            #pragma unroll
            for (int k = 0; k < 16; k++) {
                float vk = __shfl_sync(0xffffffffu, myv, k);
                acc = fmaf(vk, W2s[k * 32 + lane], acc);
            }
            rsum += fmaxf(acc, 0.f);
            rcnt += 1.f;
        }
    }
    if (cur >= 0) {
        atomicAdd(&g_pool[cur * 32 + lane], rsum);
        if (lane == 0) atomicAdd(&g_cnt[cur], rcnt);
    }
}

// ---------------------------------------------------------------------------
// 7) MLP head
// ---------------------------------------------------------------------------
__global__ __launch_bounds__(64) void k_mlp(const float* __restrict__ Wf1,
                                            const float* __restrict__ bf1,
                                            const float* __restrict__ Wf2,
                                            const float* __restrict__ bf2,
                                            float* __restrict__ out) {
    int g = threadIdx.x;
    if (g >= N_GRAPHS) return;

    float inv = 1.0f / fmaxf(g_cnt[g], 1.0f);
    float gv[32];
    #pragma unroll
    for (int c = 0; c < 32; c++) gv[c] = g_pool[g * 32 + c] * inv;

    float h[64];
    #pragma unroll 8
    for (int j = 0; j < 64; j++) {
        float s = __ldg(&bf1[j]);
        #pragma unroll
        for (int c = 0; c < 32; c++) s = fmaf(gv[c], __ldg(&Wf1[c * 64 + j]), s);
        h[j] = fmaxf(s, 0.f);
    }

    #pragma unroll
    for (int o = 0; o < 8; o++) {
        float s = __ldg(&bf2[o]);
        #pragma unroll 16
        for (int j = 0; j < 64; j++) s = fmaf(h[j], __ldg(&Wf2[j * 8 + o]), s);
        out[g * 8 + o] = s;
    }
}

// ---------------------------------------------------------------------------
// Launch (k_agg1 at slot 4 -> profiled next round)
// ---------------------------------------------------------------------------
extern "C" void kernel_launch(void* const* d_in, const int* in_sizes, int n_in,
                              void* d_out, int out_size) {
    const float* x     = (const float*)d_in[0];
    const int*   ei    = (const int*)  d_in[1];
    const int*   batch = (const int*)  d_in[2];
    const float* W1    = (const float*)d_in[3];
    const float* b1    = (const float*)d_in[4];
    const float* W2    = (const float*)d_in[5];
    const float* b2    = (const float*)d_in[6];
    const float* Wf1   = (const float*)d_in[7];
    const float* bf1   = (const float*)d_in[8];
    const float* Wf2   = (const float*)d_in[9];
    const float* bf2   = (const float*)d_in[10];
    float* out = (float*)d_out;

    int N = in_sizes[0] / 128;
    int E = in_sizes[1] / 2;
    const int* src = ei;
    const int* dst = ei + E;

    bool v4ok = ((E & 3) == 0) &&
                ((((unsigned long long)src) & 15ull) == 0) &&
                ((((unsigned long long)dst) & 15ull) == 0);
    int E4 = v4ok ? (E >> 2) : 0;

    k_init<<<CDIV(N, 256), 256>>>(N);                               // 1
    if (E4 > 0)
        k_place4<<<CDIV(E4, 256), 256>>>((const int4*)src, (const int4*)dst, E4); // 2
    else
        k_place_tail<<<CDIV(E, 256), 256>>>(src, dst, 0, E);        // 2 (fallback)
    k_gemm1<<<CDIV(N, 256), 256>>>(x, W1, N);                       // 3
    k_agg1 <<<CDIV(N, 8), 256>>>(b1, N);                            // 4 <- profiled
    k_agg2 <<<CDIV(N, 8), 256>>>(N);                                // 5
    k_pool <<<CDIV(N, 256), 256>>>(batch, W2, b2, N);               // 6
    k_mlp  <<<1, 64>>>(Wf1, bf1, Wf2, bf2, out);                    // 7
}

// round 9
// speedup vs baseline: 1.4899x; 1.0897x over previous
#include <cuda_runtime.h>

#define N_NODES_MAX 100000
#define N_GRAPHS    64
#define CAP         96          // ELL slots per node (indegree Poisson(32))
#define SPILL_MAX   8192

#define CDIV(a, b) (((a) + (b) - 1) / (b))

// ---------------------------------------------------------------------------
// Scratch (static device globals; no allocation allowed)
// ---------------------------------------------------------------------------
__device__ int    g_cur[N_NODES_MAX];           // fill cursor -> indegree
__device__ float  g_dinv[N_NODES_MAX];
__device__ int    g_ell[N_NODES_MAX * CAP];     // src ids grouped by dst
__device__ int2   g_spill[SPILL_MAX];           // (dst, src) overflow edges
__device__ int    g_spn;                        // spill count
__device__ float4 g_hs1[N_NODES_MAX * 4];       // dinv-PRESCALED layer1 feats [N,16]
__device__ float4 g_p2[N_NODES_MAX * 4];        // dinv-prescaled layer2 input
__device__ float  g_pool[N_GRAPHS * 32];
__device__ float  g_cnt[N_GRAPHS];

// ---------------------------------------------------------------------------
// 1) init: zero ELL cursors
// ---------------------------------------------------------------------------
__global__ void k_init(int n) {
    int i = blockIdx.x * blockDim.x + threadIdx.x;
    if (i < n) g_cur[i] = 0;
}

// 3) init2: zero pool / cnt / spill counter (tiny; also spaces gemm1 to slot 4)
__global__ void k_init2() {
    int i = blockIdx.x * blockDim.x + threadIdx.x;
    if (i < N_GRAPHS * 32) g_pool[i] = 0.0f;
    if (i < N_GRAPHS)      g_cnt[i]  = 0.0f;
    if (i == 0)            g_spn = 0;
}

// ---------------------------------------------------------------------------
// 2) ELL placement, 4 edges/thread (int4 loads, MLP=4 on the atomic chains)
// ---------------------------------------------------------------------------
__device__ __forceinline__ void place_one(int d, int s) {
    int pos = atomicAdd(&g_cur[d], 1);
    if (pos < CAP) {
        g_ell[d * CAP + pos] = s;
    } else {
        int sp = atomicAdd(&g_spn, 1);
        if (sp < SPILL_MAX) g_spill[sp] = make_int2(d, s);
    }
}

__global__ void k_place4(const int4* __restrict__ src4,
                         const int4* __restrict__ dst4, int E4) {
    int t = blockIdx.x * blockDim.x + threadIdx.x;
    if (t >= E4) return;
    int4 s = __ldg(&src4[t]);
    int4 d = __ldg(&dst4[t]);
    place_one(d.x, s.x);
    place_one(d.y, s.y);
    place_one(d.z, s.z);
    place_one(d.w, s.w);
}

__global__ void k_place_tail(const int* __restrict__ src,
                             const int* __restrict__ dst, int lo, int E) {
    int e = lo + blockIdx.x * blockDim.x + threadIdx.x;
    if (e >= E) return;
    place_one(__ldg(&dst[e]), __ldg(&src[e]));
}

// ---------------------------------------------------------------------------
// 4) GEMM1 (+fused dinv): hs1 = dinv * (x @ W1), dinv = rsqrt(indeg+1).
//    Runs AFTER place so g_cur holds the final indegree.
// ---------------------------------------------------------------------------
__global__ __launch_bounds__(256, 4) void k_gemm1(const float* __restrict__ x,
                                                  const float* __restrict__ W1,
                                                  int n) {
    __shared__ float4 xs[8 * 256];  // [c][row^c] 32KB
    __shared__ float4 Ws[512];      // W1: 128x16 floats = 8KB

    int tid  = threadIdx.x;
    int base = blockIdx.x * 256;
    int rg = tid >> 2;   // 0..63
    int jg = tid & 3;    // output f4 0..3

    const float4* W4 = (const float4*)W1;
    Ws[tid]       = W4[tid];
    Ws[tid + 256] = W4[tid + 256];

    const float4* x4 = (const float4*)x;
    float4 acc[4];
    #pragma unroll
    for (int rr = 0; rr < 4; rr++) acc[rr] = make_float4(0.f, 0.f, 0.f, 0.f);

    #pragma unroll
    for (int chunk = 0; chunk < 4; chunk++) {
        __syncthreads();
        #pragma unroll
        for (int m = 0; m < 8; m++) {
            int i   = m * 256 + tid;
            int row = i >> 3, c = i & 7;
            float4 v = make_float4(0.f, 0.f, 0.f, 0.f);
            if (base + row < n) v = x4[(size_t)(base + row) * 32 + chunk * 8 + c];
            xs[c * 256 + (row ^ c)] = v;
        }
        __syncthreads();

        #pragma unroll
        for (int c4 = 0; c4 < 8; c4++) {
            float4 xv[4];
            #pragma unroll
            for (int rr = 0; rr < 4; rr++)
                xv[rr] = xs[c4 * 256 + ((rr * 64 + rg) ^ c4)];
            #pragma unroll
            for (int kk = 0; kk < 4; kk++) {
                float4 w = Ws[(chunk * 32 + c4 * 4 + kk) * 4 + jg];
                #pragma unroll
                for (int rr = 0; rr < 4; rr++) {
                    float e = (kk == 0) ? xv[rr].x : (kk == 1) ? xv[rr].y
                            : (kk == 2) ? xv[rr].z : xv[rr].w;
                    acc[rr].x = fmaf(e, w.x, acc[rr].x);
                    acc[rr].y = fmaf(e, w.y, acc[rr].y);
                    acc[rr].z = fmaf(e, w.z, acc[rr].z);
                    acc[rr].w = fmaf(e, w.w, acc[rr].w);
                }
            }
        }
    }

    #pragma unroll
    for (int rr = 0; rr < 4; rr++) {
        int r = base + rr * 64 + rg;
        if (r < n) {
            float din = rsqrtf((float)(g_cur[r] + 1));
            if (jg == 0) g_dinv[r] = din;
            g_hs1[r * 4 + jg] = make_float4(acc[rr].x * din, acc[rr].y * din,
                                            acc[rr].z * din, acc[rr].w * din);
        }
    }
}

// ---------------------------------------------------------------------------
// Warp-per-node aggregation core.
//    Lane l = (neighbor group l>>2, feature chunk l&3). Per round the warp
//    gathers 8 neighbors x 16B (full 32-lane LDG), unroll 2 -> 16/iter.
//    shfl_xor(4/8/16) butterfly: EVERY lane ends with the sum for chunk l&3.
// ---------------------------------------------------------------------------
__device__ __forceinline__ float4 agg_warp(const float4* __restrict__ feat,
                                           int node, int lane) {
    int grp = lane >> 2;
    int c   = lane & 3;
    int cnt  = g_cur[node];
    int m    = min(cnt, CAP);
    int base = node * CAP;

    float4 a = make_float4(0.f, 0.f, 0.f, 0.f);

    int j = 0;
    for (; j + 16 <= m; j += 16) {
        int s0 = __ldg(&g_ell[base + j + grp]);
        int s1 = __ldg(&g_ell[base + j + 8 + grp]);
        float4 v0 = __ldg(&feat[s0 * 4 + c]);
        float4 v1 = __ldg(&feat[s1 * 4 + c]);
        a.x += v0.x + v1.x; a.y += v0.y + v1.y;
        a.z += v0.z + v1.z; a.w += v0.w + v1.w;
    }
    for (; j < m; j += 8) {
        int jj = j + grp;
        if (jj < m) {
            int s = __ldg(&g_ell[base + jj]);
            float4 v = __ldg(&feat[s * 4 + c]);
            a.x += v.x; a.y += v.y; a.z += v.z; a.w += v.w;
        }
    }
    if (cnt > CAP && grp == 0) {   // rare overflow: lanes 0-3 scan spill list
        int spn = min(g_spn, SPILL_MAX);
        for (int k = 0; k < spn; k++) {
            int2 e = g_spill[k];
            if (e.x == node) {
                float4 v = feat[e.y * 4 + c];
                a.x += v.x; a.y += v.y; a.z += v.z; a.w += v.w;
            }
        }
    }

    #pragma unroll
    for (int off = 4; off < 32; off <<= 1) {
        a.x += __shfl_xor_sync(0xffffffffu, a.x, off);
        a.y += __shfl_xor_sync(0xffffffffu, a.y, off);
        a.z += __shfl_xor_sync(0xffffffffu, a.z, off);
        a.w += __shfl_xor_sync(0xffffffffu, a.w, off);
    }
    return a;   // all lanes: sum for chunk (lane & 3)
}

// 5) Layer-1 aggregation + epilogue: p2 = dinv * relu(dinv*(self+Σ) + b1)
__global__ __launch_bounds__(256) void k_agg1(const float* __restrict__ b1, int n) {
    int node = blockIdx.x * 8 + (threadIdx.x >> 5);
    if (node >= n) return;
    int lane = threadIdx.x & 31;

    float4 a = agg_warp(g_hs1, node, lane);

    if (lane < 4) {
        int c = lane;
        float4 self = g_hs1[node * 4 + c];
        a.x += self.x; a.y += self.y; a.z += self.z; a.w += self.w;
        float din = g_dinv[node];
        float4 bb = __ldg(&((const float4*)b1)[c]);
        float4 o;
        o.x = din * fmaxf(fmaf(din, a.x, bb.x), 0.f);
        o.y = din * fmaxf(fmaf(din, a.y, bb.y), 0.f);
        o.z = din * fmaxf(fmaf(din, a.z, bb.z), 0.f);
        o.w = din * fmaxf(fmaf(din, a.w, bb.w), 0.f);
        g_p2[node * 4 + c] = o;
    }
}

// ---------------------------------------------------------------------------
// 6) Fused layer-2 aggregation + GEMM (@W2 + b2 + relu) + global mean pool.
//    Warp-per-node gather/reduce, then every lane computes one of the 32
//    output features via 16 shfl broadcasts; per-block smem accumulation
//    over the 8 sorted nodes, flush with <=few graph atomics.
// ---------------------------------------------------------------------------
__global__ __launch_bounds__(256) void k_agg2pool(const int* __restrict__ batch,
                                                  const float* __restrict__ W2,
                                                  const float* __restrict__ b2,
                                                  int n) {
    __shared__ float W2s[512];     // 16x32
    __shared__ float sp[8][32];    // per-warp node outputs
    __shared__ int   sg[8];        // per-warp graph ids (-1 = invalid)

    int tid  = threadIdx.x;
    int lane = tid & 31;
    int w    = tid >> 5;
    int node = blockIdx.x * 8 + w;

    #pragma unroll
    for (int i = tid; i < 512; i += 256) W2s[i] = W2[i];

    float out = 0.f;
    int gid = -1;

    if (node < n) {
        float4 a = agg_warp(g_p2, node, lane);
        // self term (all lanes: chunk lane&3)
        float4 self = g_p2[node * 4 + (lane & 3)];
        a.x += self.x; a.y += self.y; a.z += self.z; a.w += self.w;
        float din = g_dinv[node];
        a.x *= din; a.y *= din; a.z *= din; a.w *= din;

        gid = __ldg(&batch[node]);
        __syncthreads();   // W2s ready (uniform: all warps with node<n... see below)
        float acc = __ldg(&b2[lane]);
        #pragma unroll
        for (int k = 0; k < 16; k++) {
            float comp = ((k & 3) == 0) ? a.x : ((k & 3) == 1) ? a.y
                       : ((k & 3) == 2) ? a.z : a.w;
            float v = __shfl_sync(0xffffffffu, comp, k >> 2);
            acc = fmaf(v, W2s[k * 32 + lane], acc);
        }
        out = fmaxf(acc, 0.f);
    } else {
        __syncthreads();   // matching barrier for inactive warps
    }

    sp[w][lane] = out;
    if (lane == 0) sg[w] = gid;
    __syncthreads();

    if (w == 0) {  // warp 0 reduces the 8 rows (batch sorted -> few graphs)
        int cur = -1; float rs = 0.f, rc = 0.f;
        #pragma unroll
        for (int r = 0; r < 8; r++) {
            int g = sg[r];
            if (g < 0) continue;
            if (g != cur) {
                if (cur >= 0) {
                    atomicAdd(&g_pool[cur * 32 + lane], rs);
                    if (lane == 0) atomicAdd(&g_cnt[cur], rc);
                }
                cur = g; rs = 0.f; rc = 0.f;
            }
            rs += sp[r][lane];
            rc += 1.f;
        }
        if (cur >= 0) {
            atomicAdd(&g_pool[cur * 32 + lane], rs);
            if (lane == 0) atomicAdd(&g_cnt[cur], rc);
        }
    }
}

// ---------------------------------------------------------------------------
// 7) MLP head
// ---------------------------------------------------------------------------
__global__ __launch_bounds__(64) void k_mlp(const float* __restrict__ Wf1,
                                            const float* __restrict__ bf1,
                                            const float* __restrict__ Wf2,
                                            const float* __restrict__ bf2,
                                            float* __restrict__ out) {
    int g = threadIdx.x;
    if (g >= N_GRAPHS) return;

    float inv = 1.0f / fmaxf(g_cnt[g], 1.0f);
    float gv[32];
    #pragma unroll
    for (int c = 0; c < 32; c++) gv[c] = g_pool[g * 32 + c] * inv;

    float h[64];
    #pragma unroll 8
    for (int j = 0; j < 64; j++) {
        float s = __ldg(&bf1[j]);
        #pragma unroll
        for (int c = 0; c < 32; c++) s = fmaf(gv[c], __ldg(&Wf1[c * 64 + j]), s);
        h[j] = fmaxf(s, 0.f);
    }

    #pragma unroll
    for (int o = 0; o < 8; o++) {
        float s = __ldg(&bf2[o]);
        #pragma unroll 16
        for (int j = 0; j < 64; j++) s = fmaf(h[j], __ldg(&Wf2[j * 8 + o]), s);
        out[g * 8 + o] = s;
    }
}

// ---------------------------------------------------------------------------
// Launch (k_gemm1 at slot 4 -> profiled next round)
// ---------------------------------------------------------------------------
extern "C" void kernel_launch(void* const* d_in, const int* in_sizes, int n_in,
                              void* d_out, int out_size) {
    const float* x     = (const float*)d_in[0];
    const int*   ei    = (const int*)  d_in[1];
    const int*   batch = (const int*)  d_in[2];
    const float* W1    = (const float*)d_in[3];
    const float* b1    = (const float*)d_in[4];
    const float* W2    = (const float*)d_in[5];
    const float* b2    = (const float*)d_in[6];
    const float* Wf1   = (const float*)d_in[7];
    const float* bf1   = (const float*)d_in[8];
    const float* Wf2   = (const float*)d_in[9];
    const float* bf2   = (const float*)d_in[10];
    float* out = (float*)d_out;

    int N = in_sizes[0] / 128;
    int E = in_sizes[1] / 2;
    const int* src = ei;
    const int* dst = ei + E;

    bool v4ok = ((E & 3) == 0) &&
                ((((unsigned long long)src) & 15ull) == 0) &&
                ((((unsigned long long)dst) & 15ull) == 0);
    int E4 = v4ok ? (E >> 2) : 0;

    k_init<<<CDIV(N, 256), 256>>>(N);                               // 1
    if (E4 > 0)
        k_place4<<<CDIV(E4, 256), 256>>>((const int4*)src, (const int4*)dst, E4); // 2
    else
        k_place_tail<<<CDIV(E, 256), 256>>>(src, dst, 0, E);        // 2 (fallback)
    k_init2<<<8, 256>>>();                                          // 3
    k_gemm1<<<CDIV(N, 256), 256>>>(x, W1, N);                       // 4 <- profiled
    k_agg1 <<<CDIV(N, 8), 256>>>(b1, N);                            // 5
    k_agg2pool<<<CDIV(N, 8), 256>>>(batch, W2, b2, N);              // 6
    k_mlp  <<<1, 64>>>(Wf1, bf1, Wf2, bf2, out);                    // 7
}